// round 1
// baseline (speedup 1.0000x reference)
#include <cuda_runtime.h>
#include <math.h>

#define D_MODEL 1024
#define N_TOK   4096
#define N_HEADS 16
#define HD      64
#define D_FF    4096
#define SEQ     2048

// ---------------- scratch (device globals; no allocation allowed) ----------
__device__ float g_xn[N_TOK * D_MODEL];
__device__ float g_q [N_TOK * D_MODEL];
__device__ float g_k [N_TOK * D_MODEL];
__device__ float g_v [N_TOK * D_MODEL];
__device__ float g_at[N_TOK * D_MODEL];
__device__ float g_x1[N_TOK * D_MODEL];
__device__ float g_h1[N_TOK * D_FF];
__device__ float g_h2[N_TOK * D_FF];

// ---------------- rmsnorm: one block per row of 1024 ----------------------
__global__ void __launch_bounds__(256) rmsnorm_kernel(
    const float* __restrict__ x, const float* __restrict__ w,
    float* __restrict__ y)
{
    int row = blockIdx.x;
    int t   = threadIdx.x;                       // 256 threads, float4 each
    const float4* xr = (const float4*)(x + (size_t)row * D_MODEL);
    float4 v = xr[t];
    float ss = v.x * v.x + v.y * v.y + v.z * v.z + v.w * v.w;
    #pragma unroll
    for (int m = 16; m; m >>= 1) ss += __shfl_xor_sync(0xffffffffu, ss, m);
    __shared__ float red[8];
    if ((t & 31) == 0) red[t >> 5] = ss;
    __syncthreads();
    float tot = 0.f;
    #pragma unroll
    for (int i = 0; i < 8; i++) tot += red[i];
    float r = rsqrtf(tot * (1.0f / D_MODEL) + 1e-6f);
    float4 wv = ((const float4*)w)[t];
    float4 o;
    o.x = v.x * wv.x * r; o.y = v.y * wv.y * r;
    o.z = v.z * wv.z * r; o.w = v.w * wv.w * r;
    ((float4*)(y + (size_t)row * D_MODEL))[t] = o;
}

// ---------------- SGEMM: C[M,N] = A[M,K]@B[K,N] (+bias)(+res) -------------
// 128x128 block tile, BK=8, 256 threads, 8x8 per-thread micro-tile.
__global__ void __launch_bounds__(256) sgemm_kernel(
    const float* __restrict__ A, const float* __restrict__ B,
    const float* __restrict__ bias, const float* __restrict__ res,
    float* __restrict__ C, int M, int N, int K)
{
    __shared__ float As[8][132];   // transposed A tile, padded
    __shared__ float Bs[8][132];

    int tid = threadIdx.x;
    int tx  = tid & 15;            // 0..15 -> col group
    int ty  = tid >> 4;            // 0..15 -> row group
    int row0 = blockIdx.y * 128;
    int col0 = blockIdx.x * 128;

    float acc[8][8];
    #pragma unroll
    for (int i = 0; i < 8; i++)
        #pragma unroll
        for (int j = 0; j < 8; j++) acc[i][j] = 0.f;

    int ar = tid >> 1, ac = (tid & 1) * 4;       // A tile load coords
    int br = tid >> 5, bc = (tid & 31) * 4;      // B tile load coords
    const float* Aptr = A + (size_t)(row0 + ar) * K + ac;
    const float* Bptr = B + (size_t)br * N + col0 + bc;

    for (int k0 = 0; k0 < K; k0 += 8) {
        float4 av = *(const float4*)(Aptr + k0);
        float4 bv = *(const float4*)(Bptr + (size_t)k0 * N);
        As[ac + 0][ar] = av.x;
        As[ac + 1][ar] = av.y;
        As[ac + 2][ar] = av.z;
        As[ac + 3][ar] = av.w;
        *(float4*)&Bs[br][bc] = bv;
        __syncthreads();
        #pragma unroll
        for (int k = 0; k < 8; k++) {
            float a[8], b[8];
            *(float4*)(a)     = *(const float4*)&As[k][ty * 8];
            *(float4*)(a + 4) = *(const float4*)&As[k][ty * 8 + 4];
            *(float4*)(b)     = *(const float4*)&Bs[k][tx * 8];
            *(float4*)(b + 4) = *(const float4*)&Bs[k][tx * 8 + 4];
            #pragma unroll
            for (int i = 0; i < 8; i++)
                #pragma unroll
                for (int j = 0; j < 8; j++)
                    acc[i][j] += a[i] * b[j];
        }
        __syncthreads();
    }

    // epilogue: optional bias (per col) and residual (same shape as C)
    #pragma unroll
    for (int i = 0; i < 8; i++) {
        int r = row0 + ty * 8 + i;
        float* Crow = C + (size_t)r * N + col0 + tx * 8;
        #pragma unroll
        for (int j = 0; j < 8; j += 4) {
            float4 v;
            v.x = acc[i][j + 0]; v.y = acc[i][j + 1];
            v.z = acc[i][j + 2]; v.w = acc[i][j + 3];
            if (bias) {
                const float* bp = bias + col0 + tx * 8 + j;
                v.x += bp[0]; v.y += bp[1]; v.z += bp[2]; v.w += bp[3];
            }
            if (res) {
                float4 rv = *(const float4*)(res + (size_t)r * N + col0 + tx * 8 + j);
                v.x += rv.x; v.y += rv.y; v.z += rv.z; v.w += rv.w;
            }
            *(float4*)(Crow + j) = v;
        }
    }
}

// ---------------- flash attention: 64x64 tiles, online softmax ------------
#define QS 68      // padded stride for transposed Q/K/P tiles
#define VSs 64     // stride for V tile (natural)
#define FLASH_SMEM ((3 * 64 * QS + 64 * VSs) * 4)

__global__ void __launch_bounds__(256) flash_kernel(
    const float* __restrict__ Q, const float* __restrict__ Kg,
    const float* __restrict__ Vg, float* __restrict__ O)
{
    extern __shared__ float sm[];
    float* Qt = sm;                  // [64 hd][64 q]   transposed
    float* Kt = Qt + 64 * QS;        // [64 hd][64 kv]  transposed
    float* Pt = Kt + 64 * QS;        // [64 kv][64 q]   transposed
    float* Vs = Pt + 64 * QS;        // [64 kv][64 hd]  natural

    int tid = threadIdx.x;
    int tx = tid & 15;               // kv-col / hd-col group
    int ty = tid >> 4;               // q-row group
    int bq = blockIdx.x, head = blockIdx.y, b = blockIdx.z;
    size_t qtok0 = (size_t)b * SEQ + (size_t)bq * 64;
    int col0 = head * HD;
    const float inv_scale = 0.125f;  // 1/sqrt(64)

    // load Q tile, transposed + pre-scaled
    #pragma unroll
    for (int j = 0; j < 4; j++) {
        int f = tid + j * 256;             // float4 index 0..1023
        int r = f >> 4;
        int c = (f & 15) * 4;
        float4 v = *(const float4*)(Q + (qtok0 + r) * D_MODEL + col0 + c);
        Qt[(c + 0) * QS + r] = v.x * inv_scale;
        Qt[(c + 1) * QS + r] = v.y * inv_scale;
        Qt[(c + 2) * QS + r] = v.z * inv_scale;
        Qt[(c + 3) * QS + r] = v.w * inv_scale;
    }

    float o[4][4];
    float mrow[4], lrow[4];
    #pragma unroll
    for (int i = 0; i < 4; i++) {
        mrow[i] = -INFINITY; lrow[i] = 0.f;
        #pragma unroll
        for (int j = 0; j < 4; j++) o[i][j] = 0.f;
    }

    for (int kv = 0; kv < SEQ / 64; kv++) {
        __syncthreads();   // protect Kt/Vs/Pt from previous iteration readers
        size_t ktok0 = (size_t)b * SEQ + (size_t)kv * 64;
        #pragma unroll
        for (int j = 0; j < 4; j++) {
            int f = tid + j * 256;
            int r = f >> 4;
            int c = (f & 15) * 4;
            float4 kvv = *(const float4*)(Kg + (ktok0 + r) * D_MODEL + col0 + c);
            Kt[(c + 0) * QS + r] = kvv.x;
            Kt[(c + 1) * QS + r] = kvv.y;
            Kt[(c + 2) * QS + r] = kvv.z;
            Kt[(c + 3) * QS + r] = kvv.w;
            float4 vv = *(const float4*)(Vg + (ktok0 + r) * D_MODEL + col0 + c);
            *(float4*)&Vs[r * VSs + c] = vv;
        }
        __syncthreads();

        // S = Qt^T Kt  (per-thread 4x4)
        float s[4][4];
        #pragma unroll
        for (int i = 0; i < 4; i++)
            #pragma unroll
            for (int j = 0; j < 4; j++) s[i][j] = 0.f;
        #pragma unroll 8
        for (int kk = 0; kk < 64; kk++) {
            float4 q4 = *(const float4*)&Qt[kk * QS + ty * 4];
            float4 k4 = *(const float4*)&Kt[kk * QS + tx * 4];
            float qa[4] = {q4.x, q4.y, q4.z, q4.w};
            float kb[4] = {k4.x, k4.y, k4.z, k4.w};
            #pragma unroll
            for (int rr = 0; rr < 4; rr++)
                #pragma unroll
                for (int cc = 0; cc < 4; cc++)
                    s[rr][cc] += qa[rr] * kb[cc];
        }

        // online softmax per q-row; reduce across the 16 threads with same ty
        #pragma unroll
        for (int rr = 0; rr < 4; rr++) {
            float mx = fmaxf(fmaxf(s[rr][0], s[rr][1]), fmaxf(s[rr][2], s[rr][3]));
            #pragma unroll
            for (int m = 8; m; m >>= 1)
                mx = fmaxf(mx, __shfl_xor_sync(0xffffffffu, mx, m));
            float mnew  = fmaxf(mrow[rr], mx);
            float alpha = __expf(mrow[rr] - mnew);
            float p[4], lsum = 0.f;
            #pragma unroll
            for (int cc = 0; cc < 4; cc++) {
                p[cc] = __expf(s[rr][cc] - mnew);
                lsum += p[cc];
            }
            #pragma unroll
            for (int m = 8; m; m >>= 1)
                lsum += __shfl_xor_sync(0xffffffffu, lsum, m);
            lrow[rr] = lrow[rr] * alpha + lsum;
            mrow[rr] = mnew;
            #pragma unroll
            for (int cc = 0; cc < 4; cc++) o[rr][cc] *= alpha;
            #pragma unroll
            for (int cc = 0; cc < 4; cc++)
                Pt[(tx * 4 + cc) * QS + ty * 4 + rr] = p[cc];
        }
        __syncthreads();

        // O += P @ V
        #pragma unroll 8
        for (int c = 0; c < 64; c++) {
            float4 p4 = *(const float4*)&Pt[c * QS + ty * 4];
            float4 v4 = *(const float4*)&Vs[c * VSs + tx * 4];
            float pa[4] = {p4.x, p4.y, p4.z, p4.w};
            float vb[4] = {v4.x, v4.y, v4.z, v4.w};
            #pragma unroll
            for (int rr = 0; rr < 4; rr++)
                #pragma unroll
                for (int cc = 0; cc < 4; cc++)
                    o[rr][cc] += pa[rr] * vb[cc];
        }
    }

    // normalize and write
    #pragma unroll
    for (int rr = 0; rr < 4; rr++) {
        float inv_l = 1.f / lrow[rr];
        float4 ov;
        ov.x = o[rr][0] * inv_l; ov.y = o[rr][1] * inv_l;
        ov.z = o[rr][2] * inv_l; ov.w = o[rr][3] * inv_l;
        *(float4*)(O + (qtok0 + ty * 4 + rr) * D_MODEL + col0 + tx * 4) = ov;
    }
}

// ---------------- silu(h1) * h2 -> h1 --------------------------------------
__global__ void __launch_bounds__(256) silu_mul_kernel(
    float* __restrict__ h1, const float* __restrict__ h2, int n4)
{
    int i = blockIdx.x * blockDim.x + threadIdx.x;
    if (i < n4) {
        float4 a = ((const float4*)h1)[i];
        float4 c = ((const float4*)h2)[i];
        a.x = a.x / (1.f + __expf(-a.x)) * c.x;
        a.y = a.y / (1.f + __expf(-a.y)) * c.y;
        a.z = a.z / (1.f + __expf(-a.z)) * c.z;
        a.w = a.w / (1.f + __expf(-a.w)) * c.w;
        ((float4*)h1)[i] = a;
    }
}

// ---------------- driver ----------------------------------------------------
extern "C" void kernel_launch(void* const* d_in, const int* in_sizes, int n_in,
                              void* d_out, int out_size)
{
    const float* x       = (const float*)d_in[0];
    const float* W_q     = (const float*)d_in[1];
    const float* W_k     = (const float*)d_in[2];
    const float* W_v     = (const float*)d_in[3];
    const float* W_o     = (const float*)d_in[4];
    const float* b_o     = (const float*)d_in[5];
    const float* a_nw    = (const float*)d_in[6];
    const float* f_nw    = (const float*)d_in[7];
    const float* W_gate  = (const float*)d_in[8];
    const float* W_hid   = (const float*)d_in[9];
    const float* W_out   = (const float*)d_in[10];
    const float* b_out   = (const float*)d_in[11];
    float* out = (float*)d_out;

    float *xn, *q, *k, *v, *at, *x1, *h1, *h2;
    cudaGetSymbolAddress((void**)&xn, g_xn);
    cudaGetSymbolAddress((void**)&q,  g_q);
    cudaGetSymbolAddress((void**)&k,  g_k);
    cudaGetSymbolAddress((void**)&v,  g_v);
    cudaGetSymbolAddress((void**)&at, g_at);
    cudaGetSymbolAddress((void**)&x1, g_x1);
    cudaGetSymbolAddress((void**)&h1, g_h1);
    cudaGetSymbolAddress((void**)&h2, g_h2);

    cudaFuncSetAttribute(flash_kernel,
                         cudaFuncAttributeMaxDynamicSharedMemorySize, FLASH_SMEM);

    // 1) attn rmsnorm
    rmsnorm_kernel<<<N_TOK, 256>>>(x, a_nw, xn);

    // 2) q, k, v projections
    dim3 gd(D_MODEL / 128, N_TOK / 128);
    sgemm_kernel<<<gd, 256>>>(xn, W_q, nullptr, nullptr, q, N_TOK, D_MODEL, D_MODEL);
    sgemm_kernel<<<gd, 256>>>(xn, W_k, nullptr, nullptr, k, N_TOK, D_MODEL, D_MODEL);
    sgemm_kernel<<<gd, 256>>>(xn, W_v, nullptr, nullptr, v, N_TOK, D_MODEL, D_MODEL);

    // 3) attention
    dim3 ga(SEQ / 64, N_HEADS, 2);
    flash_kernel<<<ga, 256, FLASH_SMEM>>>(q, k, v, at);

    // 4) output projection + bias + residual
    sgemm_kernel<<<gd, 256>>>(at, W_o, b_o, x, x1, N_TOK, D_MODEL, D_MODEL);

    // 5) ffn rmsnorm
    rmsnorm_kernel<<<N_TOK, 256>>>(x1, f_nw, xn);

    // 6) gate / hidden projections
    dim3 gf(D_FF / 128, N_TOK / 128);
    sgemm_kernel<<<gf, 256>>>(xn, W_gate, nullptr, nullptr, h1, N_TOK, D_FF, D_MODEL);
    sgemm_kernel<<<gf, 256>>>(xn, W_hid,  nullptr, nullptr, h2, N_TOK, D_FF, D_MODEL);

    // 7) silu(gate) * hidden
    int n4 = N_TOK * D_FF / 4;
    silu_mul_kernel<<<(n4 + 255) / 256, 256>>>(h1, h2, n4);

    // 8) down projection + bias + residual -> out
    sgemm_kernel<<<gd, 256>>>(h1, W_out, b_out, x1, out, N_TOK, D_MODEL, D_FF);
}

// round 2
// speedup vs baseline: 1.9951x; 1.9951x over previous
#include <cuda_runtime.h>
#include <math.h>

#define D_MODEL 1024
#define N_TOK   4096
#define N_HEADS 16
#define HD      64
#define D_FF    4096
#define SEQ     2048

// ---------------- scratch (device globals; no allocation allowed) ----------
__device__ float g_xn[N_TOK * D_MODEL];
__device__ float g_q [N_TOK * D_MODEL];
__device__ float g_k [N_TOK * D_MODEL];
__device__ float g_v [N_TOK * D_MODEL];
__device__ float g_at[N_TOK * D_MODEL];
__device__ float g_x1[N_TOK * D_MODEL];
__device__ float g_h1[N_TOK * D_FF];
__device__ float g_h2[N_TOK * D_FF];

// ---------------- helpers ---------------------------------------------------
__device__ __forceinline__ unsigned smem_u32(const void* p) {
    unsigned a;
    asm("{ .reg .u64 t; cvta.to.shared.u64 t, %1; cvt.u32.u64 %0, t; }"
        : "=r"(a) : "l"(p));
    return a;
}
__device__ __forceinline__ unsigned f2tf(float x) {
    unsigned r;
    asm("cvt.rna.tf32.f32 %0, %1;" : "=r"(r) : "f"(x));
    return r;
}

// ---------------- rmsnorm: one block per row of 1024 ----------------------
__global__ void __launch_bounds__(256) rmsnorm_kernel(
    const float* __restrict__ x, const float* __restrict__ w,
    float* __restrict__ y)
{
    int row = blockIdx.x;
    int t   = threadIdx.x;
    const float4* xr = (const float4*)(x + (size_t)row * D_MODEL);
    float4 v = xr[t];
    float ss = v.x * v.x + v.y * v.y + v.z * v.z + v.w * v.w;
    #pragma unroll
    for (int m = 16; m; m >>= 1) ss += __shfl_xor_sync(0xffffffffu, ss, m);
    __shared__ float red[8];
    if ((t & 31) == 0) red[t >> 5] = ss;
    __syncthreads();
    float tot = 0.f;
    #pragma unroll
    for (int i = 0; i < 8; i++) tot += red[i];
    float r = rsqrtf(tot * (1.0f / D_MODEL) + 1e-6f);
    float4 wv = ((const float4*)w)[t];
    float4 o;
    o.x = v.x * wv.x * r; o.y = v.y * wv.y * r;
    o.z = v.z * wv.z * r; o.w = v.w * wv.w * r;
    ((float4*)(y + (size_t)row * D_MODEL))[t] = o;
}

// ---------------- TF32 tensor-core GEMM ------------------------------------
// C[M,N] = A[M,K] @ B[K,N] (+bias)(+res). mma.sync m16n8k8 tf32.
// 128x128 block tile, BK=32, 256 threads (8 warps, 2x4), warp tile 64x32.
#define BM 128
#define BN 128
#define BK 32
#define SA 36     // As row stride (floats): 32 + 4 pad -> conflict-free ldsm
#define SB 136    // Bs row stride (floats): 128 + 8 pad -> conflict-free LDS
#define ASZ (BM * SA)   // 4608 floats per buffer
#define BSZ (BK * SB)   // 4352 floats per buffer
#define GEMM_SMEM ((2 * ASZ + 2 * BSZ) * 4)   // 71680 bytes

__global__ void __launch_bounds__(256, 1) mma_gemm_kernel(
    const float* __restrict__ A, const float* __restrict__ B,
    const float* __restrict__ bias, const float* __restrict__ res,
    float* __restrict__ C, int M, int N, int K)
{
    extern __shared__ float sm[];
    float* As = sm;               // [2][BM][SA]
    float* Bs = sm + 2 * ASZ;     // [2][BK][SB]

    const int tid  = threadIdx.x;
    const int lane = tid & 31;
    const int warp = tid >> 5;
    const int wm = (warp >> 2) * 64;   // warp row offset in tile
    const int wn = (warp & 3) * 32;    // warp col offset in tile
    const int row0 = blockIdx.y * BM;
    const int col0 = blockIdx.x * BN;

    // global tile-load coordinates
    const int am = tid >> 3;           // A row (0..31, +i*32)
    const int ak = (tid & 7) * 4;      // A col within chunk
    const int bk = tid >> 5;           // B row (0..7, +i*8)
    const int bn = (tid & 31) * 4;     // B col within tile

    const float* Ap = A + (size_t)(row0 + am) * K + ak;
    const float* Bp = B + (size_t)bk * N + col0 + bn;

    float acc[4][4][4];
    #pragma unroll
    for (int i = 0; i < 4; i++)
        #pragma unroll
        for (int j = 0; j < 4; j++)
            #pragma unroll
            for (int r = 0; r < 4; r++) acc[i][j][r] = 0.f;

    const unsigned as_u32 = smem_u32(As);
    const int KC = K / BK;

    float4 ra[4], rb[4];

    // ---- prologue: load + convert + store chunk 0 ----
    #pragma unroll
    for (int i = 0; i < 4; i++) ra[i] = *(const float4*)(Ap + (size_t)(i * 32) * K);
    #pragma unroll
    for (int i = 0; i < 4; i++) rb[i] = *(const float4*)(Bp + (size_t)(i * 8) * N);
    #pragma unroll
    for (int i = 0; i < 4; i++) {
        float4 t;
        t.x = __uint_as_float(f2tf(ra[i].x)); t.y = __uint_as_float(f2tf(ra[i].y));
        t.z = __uint_as_float(f2tf(ra[i].z)); t.w = __uint_as_float(f2tf(ra[i].w));
        *(float4*)(As + (am + i * 32) * SA + ak) = t;
    }
    #pragma unroll
    for (int i = 0; i < 4; i++) {
        float4 t;
        t.x = __uint_as_float(f2tf(rb[i].x)); t.y = __uint_as_float(f2tf(rb[i].y));
        t.z = __uint_as_float(f2tf(rb[i].z)); t.w = __uint_as_float(f2tf(rb[i].w));
        *(float4*)(Bs + (bk + i * 8) * SB + bn) = t;
    }
    __syncthreads();

    for (int c = 0; c < KC; c++) {
        const int nxt = c + 1;
        // prefetch next chunk into registers
        if (nxt < KC) {
            const float* Apn = Ap + (size_t)nxt * BK;
            const float* Bpn = Bp + (size_t)nxt * BK * N;
            #pragma unroll
            for (int i = 0; i < 4; i++) ra[i] = *(const float4*)(Apn + (size_t)(i * 32) * K);
            #pragma unroll
            for (int i = 0; i < 4; i++) rb[i] = *(const float4*)(Bpn + (size_t)(i * 8) * N);
        }

        // ---- compute on buffer (c & 1) ----
        const float* Asb = As + (c & 1) * ASZ;
        const float* Bsb = Bs + (c & 1) * BSZ;
        const unsigned asb_u32 = as_u32 + (c & 1) * ASZ * 4;

        #pragma unroll
        for (int ks = 0; ks < 4; ks++) {
            const int k0 = ks * 8;
            unsigned a[4][4];
            #pragma unroll
            for (int mf = 0; mf < 4; mf++) {
                unsigned addr = asb_u32 +
                    ((wm + mf * 16 + (lane & 15)) * SA + k0 + (lane >> 4) * 4) * 4;
                asm volatile(
                    "ldmatrix.sync.aligned.m8n8.x4.shared.b16 {%0,%1,%2,%3}, [%4];"
                    : "=r"(a[mf][0]), "=r"(a[mf][1]), "=r"(a[mf][2]), "=r"(a[mf][3])
                    : "r"(addr));
            }
            unsigned b[4][2];
            #pragma unroll
            for (int nf = 0; nf < 4; nf++) {
                const int nb = wn + nf * 8 + (lane >> 2);
                b[nf][0] = __float_as_uint(Bsb[(k0 + (lane & 3)) * SB + nb]);
                b[nf][1] = __float_as_uint(Bsb[(k0 + 4 + (lane & 3)) * SB + nb]);
            }
            #pragma unroll
            for (int mf = 0; mf < 4; mf++)
                #pragma unroll
                for (int nf = 0; nf < 4; nf++) {
                    asm volatile(
                        "mma.sync.aligned.m16n8k8.row.col.f32.tf32.tf32.f32 "
                        "{%0,%1,%2,%3}, {%4,%5,%6,%7}, {%8,%9}, {%0,%1,%2,%3};"
                        : "+f"(acc[mf][nf][0]), "+f"(acc[mf][nf][1]),
                          "+f"(acc[mf][nf][2]), "+f"(acc[mf][nf][3])
                        : "r"(a[mf][0]), "r"(a[mf][1]), "r"(a[mf][2]), "r"(a[mf][3]),
                          "r"(b[nf][0]), "r"(b[nf][1]));
                }
        }

        // ---- convert + store next chunk into the other buffer ----
        if (nxt < KC) {
            float* Asn = As + (nxt & 1) * ASZ;
            float* Bsn = Bs + (nxt & 1) * BSZ;
            #pragma unroll
            for (int i = 0; i < 4; i++) {
                float4 t;
                t.x = __uint_as_float(f2tf(ra[i].x)); t.y = __uint_as_float(f2tf(ra[i].y));
                t.z = __uint_as_float(f2tf(ra[i].z)); t.w = __uint_as_float(f2tf(ra[i].w));
                *(float4*)(Asn + (am + i * 32) * SA + ak) = t;
            }
            #pragma unroll
            for (int i = 0; i < 4; i++) {
                float4 t;
                t.x = __uint_as_float(f2tf(rb[i].x)); t.y = __uint_as_float(f2tf(rb[i].y));
                t.z = __uint_as_float(f2tf(rb[i].z)); t.w = __uint_as_float(f2tf(rb[i].w));
                *(float4*)(Bsn + (bk + i * 8) * SB + bn) = t;
            }
        }
        __syncthreads();
    }

    // ---- epilogue ----
    #pragma unroll
    for (int mf = 0; mf < 4; mf++) {
        const int r = row0 + wm + mf * 16 + (lane >> 2);
        #pragma unroll
        for (int nf = 0; nf < 4; nf++) {
            const int cc = col0 + wn + nf * 8 + (lane & 3) * 2;
            float2 v0 = make_float2(acc[mf][nf][0], acc[mf][nf][1]);
            float2 v1 = make_float2(acc[mf][nf][2], acc[mf][nf][3]);
            if (bias) {
                float2 bv = *(const float2*)(bias + cc);
                v0.x += bv.x; v0.y += bv.y;
                v1.x += bv.x; v1.y += bv.y;
            }
            if (res) {
                float2 r0 = *(const float2*)(res + (size_t)r * N + cc);
                float2 r1 = *(const float2*)(res + (size_t)(r + 8) * N + cc);
                v0.x += r0.x; v0.y += r0.y;
                v1.x += r1.x; v1.y += r1.y;
            }
            *(float2*)(C + (size_t)r * N + cc) = v0;
            *(float2*)(C + (size_t)(r + 8) * N + cc) = v1;
        }
    }
}

// ---------------- flash attention: 64x64 tiles, online softmax ------------
#define QS 68
#define VSs 64
#define FLASH_SMEM ((3 * 64 * QS + 64 * VSs) * 4)

__global__ void __launch_bounds__(256) flash_kernel(
    const float* __restrict__ Q, const float* __restrict__ Kg,
    const float* __restrict__ Vg, float* __restrict__ O)
{
    extern __shared__ float smf[];
    float* Qt = smf;
    float* Kt = Qt + 64 * QS;
    float* Pt = Kt + 64 * QS;
    float* Vs = Pt + 64 * QS;

    int tid = threadIdx.x;
    int tx = tid & 15;
    int ty = tid >> 4;
    int bq = blockIdx.x, head = blockIdx.y, b = blockIdx.z;
    size_t qtok0 = (size_t)b * SEQ + (size_t)bq * 64;
    int col0 = head * HD;
    const float inv_scale = 0.125f;

    #pragma unroll
    for (int j = 0; j < 4; j++) {
        int f = tid + j * 256;
        int r = f >> 4;
        int c = (f & 15) * 4;
        float4 v = *(const float4*)(Q + (qtok0 + r) * D_MODEL + col0 + c);
        Qt[(c + 0) * QS + r] = v.x * inv_scale;
        Qt[(c + 1) * QS + r] = v.y * inv_scale;
        Qt[(c + 2) * QS + r] = v.z * inv_scale;
        Qt[(c + 3) * QS + r] = v.w * inv_scale;
    }

    float o[4][4];
    float mrow[4], lrow[4];
    #pragma unroll
    for (int i = 0; i < 4; i++) {
        mrow[i] = -INFINITY; lrow[i] = 0.f;
        #pragma unroll
        for (int j = 0; j < 4; j++) o[i][j] = 0.f;
    }

    for (int kv = 0; kv < SEQ / 64; kv++) {
        __syncthreads();
        size_t ktok0 = (size_t)b * SEQ + (size_t)kv * 64;
        #pragma unroll
        for (int j = 0; j < 4; j++) {
            int f = tid + j * 256;
            int r = f >> 4;
            int c = (f & 15) * 4;
            float4 kvv = *(const float4*)(Kg + (ktok0 + r) * D_MODEL + col0 + c);
            Kt[(c + 0) * QS + r] = kvv.x;
            Kt[(c + 1) * QS + r] = kvv.y;
            Kt[(c + 2) * QS + r] = kvv.z;
            Kt[(c + 3) * QS + r] = kvv.w;
            float4 vv = *(const float4*)(Vg + (ktok0 + r) * D_MODEL + col0 + c);
            *(float4*)&Vs[r * VSs + c] = vv;
        }
        __syncthreads();

        float s[4][4];
        #pragma unroll
        for (int i = 0; i < 4; i++)
            #pragma unroll
            for (int j = 0; j < 4; j++) s[i][j] = 0.f;
        #pragma unroll 8
        for (int kk = 0; kk < 64; kk++) {
            float4 q4 = *(const float4*)&Qt[kk * QS + ty * 4];
            float4 k4 = *(const float4*)&Kt[kk * QS + tx * 4];
            float qa[4] = {q4.x, q4.y, q4.z, q4.w};
            float kb[4] = {k4.x, k4.y, k4.z, k4.w};
            #pragma unroll
            for (int rr = 0; rr < 4; rr++)
                #pragma unroll
                for (int cc = 0; cc < 4; cc++)
                    s[rr][cc] += qa[rr] * kb[cc];
        }

        #pragma unroll
        for (int rr = 0; rr < 4; rr++) {
            float mx = fmaxf(fmaxf(s[rr][0], s[rr][1]), fmaxf(s[rr][2], s[rr][3]));
            #pragma unroll
            for (int m = 8; m; m >>= 1)
                mx = fmaxf(mx, __shfl_xor_sync(0xffffffffu, mx, m));
            float mnew  = fmaxf(mrow[rr], mx);
            float alpha = __expf(mrow[rr] - mnew);
            float p[4], lsum = 0.f;
            #pragma unroll
            for (int cc = 0; cc < 4; cc++) {
                p[cc] = __expf(s[rr][cc] - mnew);
                lsum += p[cc];
            }
            #pragma unroll
            for (int m = 8; m; m >>= 1)
                lsum += __shfl_xor_sync(0xffffffffu, lsum, m);
            lrow[rr] = lrow[rr] * alpha + lsum;
            mrow[rr] = mnew;
            #pragma unroll
            for (int cc = 0; cc < 4; cc++) o[rr][cc] *= alpha;
            #pragma unroll
            for (int cc = 0; cc < 4; cc++)
                Pt[(tx * 4 + cc) * QS + ty * 4 + rr] = p[cc];
        }
        __syncthreads();

        #pragma unroll 8
        for (int c = 0; c < 64; c++) {
            float4 p4 = *(const float4*)&Pt[c * QS + ty * 4];
            float4 v4 = *(const float4*)&Vs[c * VSs + tx * 4];
            float pa[4] = {p4.x, p4.y, p4.z, p4.w};
            float vb[4] = {v4.x, v4.y, v4.z, v4.w};
            #pragma unroll
            for (int rr = 0; rr < 4; rr++)
                #pragma unroll
                for (int cc = 0; cc < 4; cc++)
                    o[rr][cc] += pa[rr] * vb[cc];
        }
    }

    #pragma unroll
    for (int rr = 0; rr < 4; rr++) {
        float inv_l = 1.f / lrow[rr];
        float4 ov;
        ov.x = o[rr][0] * inv_l; ov.y = o[rr][1] * inv_l;
        ov.z = o[rr][2] * inv_l; ov.w = o[rr][3] * inv_l;
        *(float4*)(O + (qtok0 + ty * 4 + rr) * D_MODEL + col0 + tx * 4) = ov;
    }
}

// ---------------- silu(h1) * h2 -> h1 --------------------------------------
__global__ void __launch_bounds__(256) silu_mul_kernel(
    float* __restrict__ h1, const float* __restrict__ h2, int n4)
{
    int i = blockIdx.x * blockDim.x + threadIdx.x;
    if (i < n4) {
        float4 a = ((const float4*)h1)[i];
        float4 c = ((const float4*)h2)[i];
        a.x = a.x / (1.f + __expf(-a.x)) * c.x;
        a.y = a.y / (1.f + __expf(-a.y)) * c.y;
        a.z = a.z / (1.f + __expf(-a.z)) * c.z;
        a.w = a.w / (1.f + __expf(-a.w)) * c.w;
        ((float4*)h1)[i] = a;
    }
}

// ---------------- driver ----------------------------------------------------
extern "C" void kernel_launch(void* const* d_in, const int* in_sizes, int n_in,
                              void* d_out, int out_size)
{
    const float* x       = (const float*)d_in[0];
    const float* W_q     = (const float*)d_in[1];
    const float* W_k     = (const float*)d_in[2];
    const float* W_v     = (const float*)d_in[3];
    const float* W_o     = (const float*)d_in[4];
    const float* b_o     = (const float*)d_in[5];
    const float* a_nw    = (const float*)d_in[6];
    const float* f_nw    = (const float*)d_in[7];
    const float* W_gate  = (const float*)d_in[8];
    const float* W_hid   = (const float*)d_in[9];
    const float* W_out   = (const float*)d_in[10];
    const float* b_out   = (const float*)d_in[11];
    float* out = (float*)d_out;

    float *xn, *q, *k, *v, *at, *x1, *h1, *h2;
    cudaGetSymbolAddress((void**)&xn, g_xn);
    cudaGetSymbolAddress((void**)&q,  g_q);
    cudaGetSymbolAddress((void**)&k,  g_k);
    cudaGetSymbolAddress((void**)&v,  g_v);
    cudaGetSymbolAddress((void**)&at, g_at);
    cudaGetSymbolAddress((void**)&x1, g_x1);
    cudaGetSymbolAddress((void**)&h1, g_h1);
    cudaGetSymbolAddress((void**)&h2, g_h2);

    cudaFuncSetAttribute(flash_kernel,
                         cudaFuncAttributeMaxDynamicSharedMemorySize, FLASH_SMEM);
    cudaFuncSetAttribute(mma_gemm_kernel,
                         cudaFuncAttributeMaxDynamicSharedMemorySize, GEMM_SMEM);

    // 1) attn rmsnorm
    rmsnorm_kernel<<<N_TOK, 256>>>(x, a_nw, xn);

    // 2) q, k, v projections
    dim3 gd(D_MODEL / BN, N_TOK / BM);
    mma_gemm_kernel<<<gd, 256, GEMM_SMEM>>>(xn, W_q, nullptr, nullptr, q, N_TOK, D_MODEL, D_MODEL);
    mma_gemm_kernel<<<gd, 256, GEMM_SMEM>>>(xn, W_k, nullptr, nullptr, k, N_TOK, D_MODEL, D_MODEL);
    mma_gemm_kernel<<<gd, 256, GEMM_SMEM>>>(xn, W_v, nullptr, nullptr, v, N_TOK, D_MODEL, D_MODEL);

    // 3) attention
    dim3 ga(SEQ / 64, N_HEADS, 2);
    flash_kernel<<<ga, 256, FLASH_SMEM>>>(q, k, v, at);

    // 4) output projection + bias + residual
    mma_gemm_kernel<<<gd, 256, GEMM_SMEM>>>(at, W_o, b_o, x, x1, N_TOK, D_MODEL, D_MODEL);

    // 5) ffn rmsnorm
    rmsnorm_kernel<<<N_TOK, 256>>>(x1, f_nw, xn);

    // 6) gate / hidden projections
    dim3 gf(D_FF / BN, N_TOK / BM);
    mma_gemm_kernel<<<gf, 256, GEMM_SMEM>>>(xn, W_gate, nullptr, nullptr, h1, N_TOK, D_FF, D_MODEL);
    mma_gemm_kernel<<<gf, 256, GEMM_SMEM>>>(xn, W_hid,  nullptr, nullptr, h2, N_TOK, D_FF, D_MODEL);

    // 7) silu(gate) * hidden
    int n4 = N_TOK * D_FF / 4;
    silu_mul_kernel<<<(n4 + 255) / 256, 256>>>(h1, h2, n4);

    // 8) down projection + bias + residual -> out
    mma_gemm_kernel<<<gd, 256, GEMM_SMEM>>>(h1, W_out, b_out, x1, out, N_TOK, D_MODEL, D_FF);
}

// round 3
// speedup vs baseline: 3.2827x; 1.6454x over previous
#include <cuda_runtime.h>
#include <cuda_fp16.h>
#include <math.h>

#define D_MODEL 1024
#define N_TOK   4096
#define N_HEADS 16
#define HD      64
#define D_FF    4096
#define SEQ     2048

// ---------------- scratch (device globals; no allocation allowed) ----------
__device__ float g_xn[N_TOK * D_MODEL];
__device__ float g_q [N_TOK * D_MODEL];
__device__ float g_k [N_TOK * D_MODEL];
__device__ float g_v [N_TOK * D_MODEL];
__device__ float g_at[N_TOK * D_MODEL];
__device__ float g_x1[N_TOK * D_MODEL];
__device__ float g_h1[N_TOK * D_FF];
__device__ float g_h2[N_TOK * D_FF];

// ---------------- helpers ---------------------------------------------------
__device__ __forceinline__ unsigned smem_u32(const void* p) {
    unsigned a;
    asm("{ .reg .u64 t; cvta.to.shared.u64 t, %1; cvt.u32.u64 %0, t; }"
        : "=r"(a) : "l"(p));
    return a;
}
__device__ __forceinline__ unsigned f2tf(float x) {
    unsigned r;
    asm("cvt.rna.tf32.f32 %0, %1;" : "=r"(r) : "f"(x));
    return r;
}
__device__ __forceinline__ float ex2f(float x) {
    float y;
    asm("ex2.approx.ftz.f32 %0, %1;" : "=f"(y) : "f"(x));
    return y;
}
__device__ __forceinline__ unsigned packh2(float lo, float hi) {
    unsigned d;
    asm("cvt.rn.f16x2.f32 %0, %1, %2;" : "=r"(d) : "f"(hi), "f"(lo));
    return d;
}
__device__ __forceinline__ void ldsm_x4(unsigned& r0, unsigned& r1,
                                        unsigned& r2, unsigned& r3, unsigned addr) {
    asm volatile("ldmatrix.sync.aligned.m8n8.x4.shared.b16 {%0,%1,%2,%3}, [%4];"
                 : "=r"(r0), "=r"(r1), "=r"(r2), "=r"(r3) : "r"(addr));
}
__device__ __forceinline__ void ldsm_x4_t(unsigned& r0, unsigned& r1,
                                          unsigned& r2, unsigned& r3, unsigned addr) {
    asm volatile("ldmatrix.sync.aligned.m8n8.x4.trans.shared.b16 {%0,%1,%2,%3}, [%4];"
                 : "=r"(r0), "=r"(r1), "=r"(r2), "=r"(r3) : "r"(addr));
}
__device__ __forceinline__ void mma_tf32(float* d, const unsigned* a,
                                         unsigned b0, unsigned b1) {
    asm volatile(
        "mma.sync.aligned.m16n8k8.row.col.f32.tf32.tf32.f32 "
        "{%0,%1,%2,%3}, {%4,%5,%6,%7}, {%8,%9}, {%0,%1,%2,%3};"
        : "+f"(d[0]), "+f"(d[1]), "+f"(d[2]), "+f"(d[3])
        : "r"(a[0]), "r"(a[1]), "r"(a[2]), "r"(a[3]), "r"(b0), "r"(b1));
}
__device__ __forceinline__ void mma_f16(float* d, unsigned a0, unsigned a1,
                                        unsigned a2, unsigned a3,
                                        unsigned b0, unsigned b1) {
    asm volatile(
        "mma.sync.aligned.m16n8k16.row.col.f32.f16.f16.f32 "
        "{%0,%1,%2,%3}, {%4,%5,%6,%7}, {%8,%9}, {%0,%1,%2,%3};"
        : "+f"(d[0]), "+f"(d[1]), "+f"(d[2]), "+f"(d[3])
        : "r"(a0), "r"(a1), "r"(a2), "r"(a3), "r"(b0), "r"(b1));
}

// ---------------- rmsnorm: one block per row of 1024 ----------------------
__global__ void __launch_bounds__(256) rmsnorm_kernel(
    const float* __restrict__ x, const float* __restrict__ w,
    float* __restrict__ y)
{
    int row = blockIdx.x;
    int t   = threadIdx.x;
    const float4* xr = (const float4*)(x + (size_t)row * D_MODEL);
    float4 v = xr[t];
    float ss = v.x * v.x + v.y * v.y + v.z * v.z + v.w * v.w;
    #pragma unroll
    for (int m = 16; m; m >>= 1) ss += __shfl_xor_sync(0xffffffffu, ss, m);
    __shared__ float red[8];
    if ((t & 31) == 0) red[t >> 5] = ss;
    __syncthreads();
    float tot = 0.f;
    #pragma unroll
    for (int i = 0; i < 8; i++) tot += red[i];
    float r = rsqrtf(tot * (1.0f / D_MODEL) + 1e-6f);
    float4 wv = ((const float4*)w)[t];
    float4 o;
    o.x = v.x * wv.x * r; o.y = v.y * wv.y * r;
    o.z = v.z * wv.z * r; o.w = v.w * wv.w * r;
    ((float4*)(y + (size_t)row * D_MODEL))[t] = o;
}

// ---------------- TF32 tensor-core GEMM (shared body) -----------------------
#define BM 128
#define BN 128
#define BK 32
#define SA 36
#define SB 136
#define ASZ (BM * SA)
#define BSZ (BK * SB)
#define GEMM_SMEM ((2 * ASZ + 2 * BSZ) * 4)

__device__ __forceinline__ void gemm_body(
    const float* __restrict__ A, const float* __restrict__ B,
    const float* __restrict__ bias, const float* __restrict__ res,
    float* __restrict__ C, int M, int N, int K)
{
    extern __shared__ float sm[];
    float* As = sm;
    float* Bs = sm + 2 * ASZ;

    const int tid  = threadIdx.x;
    const int lane = tid & 31;
    const int warp = tid >> 5;
    const int wm = (warp >> 2) * 64;
    const int wn = (warp & 3) * 32;
    const int row0 = blockIdx.y * BM;
    const int col0 = blockIdx.x * BN;

    const int am = tid >> 3;
    const int ak = (tid & 7) * 4;
    const int bk = tid >> 5;
    const int bn = (tid & 31) * 4;

    const float* Ap = A + (size_t)(row0 + am) * K + ak;
    const float* Bp = B + (size_t)bk * N + col0 + bn;

    float acc[4][4][4];
    #pragma unroll
    for (int i = 0; i < 4; i++)
        #pragma unroll
        for (int j = 0; j < 4; j++)
            #pragma unroll
            for (int r = 0; r < 4; r++) acc[i][j][r] = 0.f;

    const unsigned as_u32 = smem_u32(As);
    const int KC = K / BK;

    float4 ra[4], rb[4];

    #pragma unroll
    for (int i = 0; i < 4; i++) ra[i] = *(const float4*)(Ap + (size_t)(i * 32) * K);
    #pragma unroll
    for (int i = 0; i < 4; i++) rb[i] = *(const float4*)(Bp + (size_t)(i * 8) * N);
    #pragma unroll
    for (int i = 0; i < 4; i++) {
        float4 t;
        t.x = __uint_as_float(f2tf(ra[i].x)); t.y = __uint_as_float(f2tf(ra[i].y));
        t.z = __uint_as_float(f2tf(ra[i].z)); t.w = __uint_as_float(f2tf(ra[i].w));
        *(float4*)(As + (am + i * 32) * SA + ak) = t;
    }
    #pragma unroll
    for (int i = 0; i < 4; i++) {
        float4 t;
        t.x = __uint_as_float(f2tf(rb[i].x)); t.y = __uint_as_float(f2tf(rb[i].y));
        t.z = __uint_as_float(f2tf(rb[i].z)); t.w = __uint_as_float(f2tf(rb[i].w));
        *(float4*)(Bs + (bk + i * 8) * SB + bn) = t;
    }
    __syncthreads();

    for (int c = 0; c < KC; c++) {
        const int nxt = c + 1;
        if (nxt < KC) {
            const float* Apn = Ap + (size_t)nxt * BK;
            const float* Bpn = Bp + (size_t)nxt * BK * N;
            #pragma unroll
            for (int i = 0; i < 4; i++) ra[i] = *(const float4*)(Apn + (size_t)(i * 32) * K);
            #pragma unroll
            for (int i = 0; i < 4; i++) rb[i] = *(const float4*)(Bpn + (size_t)(i * 8) * N);
        }

        const float* Bsb = Bs + (c & 1) * BSZ;
        const unsigned asb_u32 = as_u32 + (c & 1) * ASZ * 4;

        #pragma unroll
        for (int ks = 0; ks < 4; ks++) {
            const int k0 = ks * 8;
            unsigned a[4][4];
            #pragma unroll
            for (int mf = 0; mf < 4; mf++) {
                unsigned addr = asb_u32 +
                    ((wm + mf * 16 + (lane & 15)) * SA + k0 + (lane >> 4) * 4) * 4;
                ldsm_x4(a[mf][0], a[mf][1], a[mf][2], a[mf][3], addr);
            }
            unsigned b[4][2];
            #pragma unroll
            for (int nf = 0; nf < 4; nf++) {
                const int nb = wn + nf * 8 + (lane >> 2);
                b[nf][0] = __float_as_uint(Bsb[(k0 + (lane & 3)) * SB + nb]);
                b[nf][1] = __float_as_uint(Bsb[(k0 + 4 + (lane & 3)) * SB + nb]);
            }
            #pragma unroll
            for (int mf = 0; mf < 4; mf++)
                #pragma unroll
                for (int nf = 0; nf < 4; nf++)
                    mma_tf32(acc[mf][nf], a[mf], b[nf][0], b[nf][1]);
        }

        if (nxt < KC) {
            float* Asn = As + (nxt & 1) * ASZ;
            float* Bsn = Bs + (nxt & 1) * BSZ;
            #pragma unroll
            for (int i = 0; i < 4; i++) {
                float4 t;
                t.x = __uint_as_float(f2tf(ra[i].x)); t.y = __uint_as_float(f2tf(ra[i].y));
                t.z = __uint_as_float(f2tf(ra[i].z)); t.w = __uint_as_float(f2tf(ra[i].w));
                *(float4*)(Asn + (am + i * 32) * SA + ak) = t;
            }
            #pragma unroll
            for (int i = 0; i < 4; i++) {
                float4 t;
                t.x = __uint_as_float(f2tf(rb[i].x)); t.y = __uint_as_float(f2tf(rb[i].y));
                t.z = __uint_as_float(f2tf(rb[i].z)); t.w = __uint_as_float(f2tf(rb[i].w));
                *(float4*)(Bsn + (bk + i * 8) * SB + bn) = t;
            }
        }
        __syncthreads();
    }

    #pragma unroll
    for (int mf = 0; mf < 4; mf++) {
        const int r = row0 + wm + mf * 16 + (lane >> 2);
        #pragma unroll
        for (int nf = 0; nf < 4; nf++) {
            const int cc = col0 + wn + nf * 8 + (lane & 3) * 2;
            float2 v0 = make_float2(acc[mf][nf][0], acc[mf][nf][1]);
            float2 v1 = make_float2(acc[mf][nf][2], acc[mf][nf][3]);
            if (bias) {
                float2 bv = *(const float2*)(bias + cc);
                v0.x += bv.x; v0.y += bv.y;
                v1.x += bv.x; v1.y += bv.y;
            }
            if (res) {
                float2 r0 = *(const float2*)(res + (size_t)r * N + cc);
                float2 r1 = *(const float2*)(res + (size_t)(r + 8) * N + cc);
                v0.x += r0.x; v0.y += r0.y;
                v1.x += r1.x; v1.y += r1.y;
            }
            *(float2*)(C + (size_t)r * N + cc) = v0;
            *(float2*)(C + (size_t)(r + 8) * N + cc) = v1;
        }
    }
}

__global__ void __launch_bounds__(256, 1) mma_gemm_kernel(
    const float* __restrict__ A, const float* __restrict__ B,
    const float* __restrict__ bias, const float* __restrict__ res,
    float* __restrict__ C, int M, int N, int K)
{
    gemm_body(A, B, bias, res, C, M, N, K);
}

__global__ void __launch_bounds__(256, 1) mma_gemm_multi(
    const float* __restrict__ A,
    const float* __restrict__ B0, const float* __restrict__ B1, const float* __restrict__ B2,
    float* __restrict__ C0, float* __restrict__ C1, float* __restrict__ C2,
    int M, int N, int K)
{
    const float* B = (blockIdx.z == 0) ? B0 : (blockIdx.z == 1) ? B1 : B2;
    float*       C = (blockIdx.z == 0) ? C0 : (blockIdx.z == 1) ? C1 : C2;
    gemm_body(A, B, nullptr, nullptr, C, M, N, K);
}

// ---------------- flash attention v2: tensor-core, register P ---------------
// BQ=128 (8 warps x 16 rows), BKV=64, HD=64.
// S via tf32 mma (Q frags in regs, K tf32 smem), softmax in regs,
// P -> f16 regs -> A-frag, V f16 smem -> ldmatrix.trans B-frags.
#define AQS 68   // K tile row stride (floats)
#define AVS 72   // V tile row stride (halves)
#define FL_SMEM (2 * 64 * AQS * 4 + 2 * 64 * AVS * 2)   // 53248 B

__global__ void __launch_bounds__(256) flash2_kernel(
    const float* __restrict__ Q, const float* __restrict__ Kg,
    const float* __restrict__ Vg, float* __restrict__ O)
{
    extern __shared__ char fsm[];
    float*  Kf = (float*)fsm;                          // [2][64][AQS]
    __half* Vh = (__half*)(fsm + 2 * 64 * AQS * 4);    // [2][64][AVS]

    const int tid  = threadIdx.x;
    const int lane = tid & 31;
    const int warp = tid >> 5;
    const int bq = blockIdx.x, head = blockIdx.y, b = blockIdx.z;
    const size_t qtok0 = (size_t)b * SEQ + (size_t)bq * 128;
    const size_t ktokb = (size_t)b * SEQ;
    const int col0 = head * HD;
    const int m0 = warp * 16;
    const float QSCALE = 0.125f * 1.4426950408889634f;   // 1/sqrt(64) * log2(e)

    const unsigned kf_u32 = smem_u32(Kf);
    const unsigned vh_u32 = smem_u32(Vh);

    // ---- stage Q (scaled, tf32) into the Kf area viewed as [128][AQS] ----
    #pragma unroll
    for (int j = 0; j < 8; j++) {
        int f = tid + j * 256;
        int r = f >> 4, c = (f & 15) * 4;
        float4 v = *(const float4*)(Q + (qtok0 + r) * D_MODEL + col0 + c);
        float4 t;
        t.x = __uint_as_float(f2tf(v.x * QSCALE));
        t.y = __uint_as_float(f2tf(v.y * QSCALE));
        t.z = __uint_as_float(f2tf(v.z * QSCALE));
        t.w = __uint_as_float(f2tf(v.w * QSCALE));
        *(float4*)(Kf + r * AQS + c) = t;
    }
    __syncthreads();

    // ---- Q A-fragments into registers (8 k-steps x 4 regs) ----
    unsigned qa[8][4];
    #pragma unroll
    for (int k0 = 0; k0 < 8; k0++) {
        unsigned addr = kf_u32 +
            ((m0 + (lane & 15)) * AQS + k0 * 8 + (lane >> 4) * 4) * 4;
        ldsm_x4(qa[k0][0], qa[k0][1], qa[k0][2], qa[k0][3], addr);
    }
    __syncthreads();   // Kf about to be overwritten by K tile 0

    // ---- load K/V tile 0 into buffer 0 ----
    #pragma unroll
    for (int j = 0; j < 4; j++) {
        int f = tid + j * 256;
        int r = f >> 4, c = (f & 15) * 4;
        float4 kv4 = *(const float4*)(Kg + (ktokb + r) * D_MODEL + col0 + c);
        float4 vv4 = *(const float4*)(Vg + (ktokb + r) * D_MODEL + col0 + c);
        float4 t;
        t.x = __uint_as_float(f2tf(kv4.x)); t.y = __uint_as_float(f2tf(kv4.y));
        t.z = __uint_as_float(f2tf(kv4.z)); t.w = __uint_as_float(f2tf(kv4.w));
        *(float4*)(Kf + r * AQS + c) = t;
        *(__half2*)(Vh + r * AVS + c)     = __floats2half2_rn(vv4.x, vv4.y);
        *(__half2*)(Vh + r * AVS + c + 2) = __floats2half2_rn(vv4.z, vv4.w);
    }
    __syncthreads();

    float m0s = -INFINITY, m1s = -INFINITY, l0s = 0.f, l1s = 0.f;
    float oacc[8][4];
    #pragma unroll
    for (int i = 0; i < 8; i++)
        #pragma unroll
        for (int j = 0; j < 4; j++) oacc[i][j] = 0.f;

    for (int kvt = 0; kvt < SEQ / 64; kvt++) {
        const int buf = kvt & 1;
        const bool pre = (kvt + 1) < SEQ / 64;
        float4 kr[4], vr[4];
        if (pre) {
            size_t kt = ktokb + (size_t)(kvt + 1) * 64;
            #pragma unroll
            for (int j = 0; j < 4; j++) {
                int f = tid + j * 256;
                int r = f >> 4, c = (f & 15) * 4;
                kr[j] = *(const float4*)(Kg + (kt + r) * D_MODEL + col0 + c);
                vr[j] = *(const float4*)(Vg + (kt + r) * D_MODEL + col0 + c);
            }
        }

        // ---- S = Q @ K^T (tf32 mma) ----
        float sacc[8][4];
        #pragma unroll
        for (int i = 0; i < 8; i++)
            #pragma unroll
            for (int j = 0; j < 4; j++) sacc[i][j] = 0.f;

        const unsigned kfb = kf_u32 + buf * 64 * AQS * 4;
        #pragma unroll
        for (int k0 = 0; k0 < 8; k0++) {
            #pragma unroll
            for (int nf2 = 0; nf2 < 4; nf2++) {
                const int midx = lane >> 3;
                unsigned addr = kfb +
                    ((nf2 * 16 + (midx >> 1) * 8 + (lane & 7)) * AQS +
                     k0 * 8 + (midx & 1) * 4) * 4;
                unsigned b0, b1, b2, b3;
                ldsm_x4(b0, b1, b2, b3, addr);
                mma_tf32(sacc[nf2 * 2],     qa[k0], b0, b1);
                mma_tf32(sacc[nf2 * 2 + 1], qa[k0], b2, b3);
            }
        }

        // ---- online softmax (warp-private rows) ----
        float mx0 = -INFINITY, mx1 = -INFINITY;
        #pragma unroll
        for (int nf = 0; nf < 8; nf++) {
            mx0 = fmaxf(mx0, fmaxf(sacc[nf][0], sacc[nf][1]));
            mx1 = fmaxf(mx1, fmaxf(sacc[nf][2], sacc[nf][3]));
        }
        mx0 = fmaxf(mx0, __shfl_xor_sync(0xffffffffu, mx0, 1));
        mx0 = fmaxf(mx0, __shfl_xor_sync(0xffffffffu, mx0, 2));
        mx1 = fmaxf(mx1, __shfl_xor_sync(0xffffffffu, mx1, 1));
        mx1 = fmaxf(mx1, __shfl_xor_sync(0xffffffffu, mx1, 2));

        const float mn0 = fmaxf(m0s, mx0);
        const float mn1 = fmaxf(m1s, mx1);
        const float al0 = ex2f(m0s - mn0);
        const float al1 = ex2f(m1s - mn1);

        unsigned pa0[8], pa1[8];
        float ls0 = 0.f, ls1 = 0.f;
        #pragma unroll
        for (int nf = 0; nf < 8; nf++) {
            float p0 = ex2f(sacc[nf][0] - mn0);
            float p1 = ex2f(sacc[nf][1] - mn0);
            float p2 = ex2f(sacc[nf][2] - mn1);
            float p3 = ex2f(sacc[nf][3] - mn1);
            ls0 += p0 + p1;
            ls1 += p2 + p3;
            pa0[nf] = packh2(p0, p1);
            pa1[nf] = packh2(p2, p3);
        }
        ls0 += __shfl_xor_sync(0xffffffffu, ls0, 1);
        ls0 += __shfl_xor_sync(0xffffffffu, ls0, 2);
        ls1 += __shfl_xor_sync(0xffffffffu, ls1, 1);
        ls1 += __shfl_xor_sync(0xffffffffu, ls1, 2);
        l0s = l0s * al0 + ls0;
        l1s = l1s * al1 + ls1;
        m0s = mn0; m1s = mn1;

        #pragma unroll
        for (int nf = 0; nf < 8; nf++) {
            oacc[nf][0] *= al0; oacc[nf][1] *= al0;
            oacc[nf][2] *= al1; oacc[nf][3] *= al1;
        }

        // ---- O += P @ V (f16 mma, V B-frags via ldmatrix.trans) ----
        const unsigned vhb = vh_u32 + buf * 64 * AVS * 2;
        #pragma unroll
        for (int ks = 0; ks < 4; ks++) {
            unsigned a0 = pa0[2 * ks],     a1 = pa1[2 * ks];
            unsigned a2 = pa0[2 * ks + 1], a3 = pa1[2 * ks + 1];
            #pragma unroll
            for (int no = 0; no < 4; no++) {
                unsigned addr = vhb +
                    ((ks * 16 + (lane & 15)) * AVS + no * 16 + (lane >> 4) * 8) * 2;
                unsigned b0, b1, b2, b3;
                ldsm_x4_t(b0, b1, b2, b3, addr);
                mma_f16(oacc[no * 2],     a0, a1, a2, a3, b0, b1);
                mma_f16(oacc[no * 2 + 1], a0, a1, a2, a3, b2, b3);
            }
        }

        // ---- store prefetched tile into other buffer ----
        if (pre) {
            float*  Kfd = Kf + (buf ^ 1) * 64 * AQS;
            __half* Vhd = Vh + (buf ^ 1) * 64 * AVS;
            #pragma unroll
            for (int j = 0; j < 4; j++) {
                int f = tid + j * 256;
                int r = f >> 4, c = (f & 15) * 4;
                float4 t;
                t.x = __uint_as_float(f2tf(kr[j].x)); t.y = __uint_as_float(f2tf(kr[j].y));
                t.z = __uint_as_float(f2tf(kr[j].z)); t.w = __uint_as_float(f2tf(kr[j].w));
                *(float4*)(Kfd + r * AQS + c) = t;
                *(__half2*)(Vhd + r * AVS + c)     = __floats2half2_rn(vr[j].x, vr[j].y);
                *(__half2*)(Vhd + r * AVS + c + 2) = __floats2half2_rn(vr[j].z, vr[j].w);
            }
        }
        __syncthreads();
    }

    // ---- normalize and write O ----
    const float i0 = 1.f / l0s;
    const float i1 = 1.f / l1s;
    const size_t row0 = qtok0 + m0 + (lane >> 2);
    #pragma unroll
    for (int no = 0; no < 8; no++) {
        const int cw = col0 + no * 8 + (lane & 3) * 2;
        float2 w0 = make_float2(oacc[no][0] * i0, oacc[no][1] * i0);
        float2 w1 = make_float2(oacc[no][2] * i1, oacc[no][3] * i1);
        *(float2*)(O + row0 * D_MODEL + cw)       = w0;
        *(float2*)(O + (row0 + 8) * D_MODEL + cw) = w1;
    }
}

// ---------------- silu(h1) * h2 -> h1 --------------------------------------
__global__ void __launch_bounds__(256) silu_mul_kernel(
    float* __restrict__ h1, const float* __restrict__ h2, int n4)
{
    int i = blockIdx.x * blockDim.x + threadIdx.x;
    if (i < n4) {
        float4 a = ((const float4*)h1)[i];
        float4 c = ((const float4*)h2)[i];
        a.x = a.x / (1.f + __expf(-a.x)) * c.x;
        a.y = a.y / (1.f + __expf(-a.y)) * c.y;
        a.z = a.z / (1.f + __expf(-a.z)) * c.z;
        a.w = a.w / (1.f + __expf(-a.w)) * c.w;
        ((float4*)h1)[i] = a;
    }
}

// ---------------- driver ----------------------------------------------------
extern "C" void kernel_launch(void* const* d_in, const int* in_sizes, int n_in,
                              void* d_out, int out_size)
{
    const float* x       = (const float*)d_in[0];
    const float* W_q     = (const float*)d_in[1];
    const float* W_k     = (const float*)d_in[2];
    const float* W_v     = (const float*)d_in[3];
    const float* W_o     = (const float*)d_in[4];
    const float* b_o     = (const float*)d_in[5];
    const float* a_nw    = (const float*)d_in[6];
    const float* f_nw    = (const float*)d_in[7];
    const float* W_gate  = (const float*)d_in[8];
    const float* W_hid   = (const float*)d_in[9];
    const float* W_out   = (const float*)d_in[10];
    const float* b_out   = (const float*)d_in[11];
    float* out = (float*)d_out;

    float *xn, *q, *k, *v, *at, *x1, *h1, *h2;
    cudaGetSymbolAddress((void**)&xn, g_xn);
    cudaGetSymbolAddress((void**)&q,  g_q);
    cudaGetSymbolAddress((void**)&k,  g_k);
    cudaGetSymbolAddress((void**)&v,  g_v);
    cudaGetSymbolAddress((void**)&at, g_at);
    cudaGetSymbolAddress((void**)&x1, g_x1);
    cudaGetSymbolAddress((void**)&h1, g_h1);
    cudaGetSymbolAddress((void**)&h2, g_h2);

    cudaFuncSetAttribute(flash2_kernel,
                         cudaFuncAttributeMaxDynamicSharedMemorySize, FL_SMEM);
    cudaFuncSetAttribute(mma_gemm_kernel,
                         cudaFuncAttributeMaxDynamicSharedMemorySize, GEMM_SMEM);
    cudaFuncSetAttribute(mma_gemm_multi,
                         cudaFuncAttributeMaxDynamicSharedMemorySize, GEMM_SMEM);

    // 1) attn rmsnorm
    rmsnorm_kernel<<<N_TOK, 256>>>(x, a_nw, xn);

    // 2) q, k, v projections (one batched launch)
    dim3 gqkv(D_MODEL / BN, N_TOK / BM, 3);
    mma_gemm_multi<<<gqkv, 256, GEMM_SMEM>>>(xn, W_q, W_k, W_v, q, k, v,
                                             N_TOK, D_MODEL, D_MODEL);

    // 3) attention
    dim3 ga(SEQ / 128, N_HEADS, 2);
    flash2_kernel<<<ga, 256, FL_SMEM>>>(q, k, v, at);

    // 4) output projection + bias + residual
    dim3 gd(D_MODEL / BN, N_TOK / BM);
    mma_gemm_kernel<<<gd, 256, GEMM_SMEM>>>(at, W_o, b_o, x, x1,
                                            N_TOK, D_MODEL, D_MODEL);

    // 5) ffn rmsnorm
    rmsnorm_kernel<<<N_TOK, 256>>>(x1, f_nw, xn);

    // 6) gate / hidden projections (one batched launch)
    dim3 gf(D_FF / BN, N_TOK / BM, 2);
    mma_gemm_multi<<<gf, 256, GEMM_SMEM>>>(xn, W_gate, W_hid, W_hid, h1, h2, h2,
                                           N_TOK, D_FF, D_MODEL);

    // 7) silu(gate) * hidden
    int n4 = N_TOK * D_FF / 4;
    silu_mul_kernel<<<(n4 + 255) / 256, 256>>>(h1, h2, n4);

    // 8) down projection + bias + residual -> out
    mma_gemm_kernel<<<gd, 256, GEMM_SMEM>>>(h1, W_out, b_out, x1, out,
                                            N_TOK, D_MODEL, D_FF);
}

// round 4
// speedup vs baseline: 6.0800x; 1.8521x over previous
#include <cuda_runtime.h>
#include <cuda_fp16.h>
#include <cuda_bf16.h>
#include <math.h>

#define D_MODEL 1024
#define N_TOK   4096
#define N_HEADS 16
#define HD      64
#define D_FF    4096
#define SEQ     2048

// ---------------- scratch (device globals; no allocation allowed) ----------
__device__ float g_q [N_TOK * D_MODEL];
__device__ float g_k [N_TOK * D_MODEL];
__device__ float g_v [N_TOK * D_MODEL];
__device__ float g_x1[N_TOK * D_MODEL];
__device__ float g_h1[N_TOK * D_FF];
__device__ float g_h2[N_TOK * D_FF];
__device__ __nv_bfloat16 g_xnb[N_TOK * D_MODEL];
__device__ __nv_bfloat16 g_atb[N_TOK * D_MODEL];
__device__ __nv_bfloat16 g_hb [N_TOK * D_FF];
__device__ __nv_bfloat16 g_wq[D_MODEL * D_MODEL];
__device__ __nv_bfloat16 g_wk[D_MODEL * D_MODEL];
__device__ __nv_bfloat16 g_wv[D_MODEL * D_MODEL];
__device__ __nv_bfloat16 g_wo[D_MODEL * D_MODEL];
__device__ __nv_bfloat16 g_wg[D_MODEL * D_FF];
__device__ __nv_bfloat16 g_wh[D_MODEL * D_FF];
__device__ __nv_bfloat16 g_wd[D_FF * D_MODEL];

// ---------------- helpers ---------------------------------------------------
__device__ __forceinline__ unsigned smem_u32(const void* p) {
    unsigned a;
    asm("{ .reg .u64 t; cvta.to.shared.u64 t, %1; cvt.u32.u64 %0, t; }"
        : "=r"(a) : "l"(p));
    return a;
}
__device__ __forceinline__ unsigned f2tf(float x) {
    unsigned r;
    asm("cvt.rna.tf32.f32 %0, %1;" : "=r"(r) : "f"(x));
    return r;
}
__device__ __forceinline__ float ex2f(float x) {
    float y;
    asm("ex2.approx.ftz.f32 %0, %1;" : "=f"(y) : "f"(x));
    return y;
}
__device__ __forceinline__ unsigned packh2(float lo, float hi) {
    unsigned d;
    asm("cvt.rn.f16x2.f32 %0, %1, %2;" : "=r"(d) : "f"(hi), "f"(lo));
    return d;
}
__device__ __forceinline__ void ldsm_x4(unsigned& r0, unsigned& r1,
                                        unsigned& r2, unsigned& r3, unsigned addr) {
    asm volatile("ldmatrix.sync.aligned.m8n8.x4.shared.b16 {%0,%1,%2,%3}, [%4];"
                 : "=r"(r0), "=r"(r1), "=r"(r2), "=r"(r3) : "r"(addr));
}
__device__ __forceinline__ void ldsm_x4_t(unsigned& r0, unsigned& r1,
                                          unsigned& r2, unsigned& r3, unsigned addr) {
    asm volatile("ldmatrix.sync.aligned.m8n8.x4.trans.shared.b16 {%0,%1,%2,%3}, [%4];"
                 : "=r"(r0), "=r"(r1), "=r"(r2), "=r"(r3) : "r"(addr));
}
__device__ __forceinline__ void mma_tf32(float* d, const unsigned* a,
                                         unsigned b0, unsigned b1) {
    asm volatile(
        "mma.sync.aligned.m16n8k8.row.col.f32.tf32.tf32.f32 "
        "{%0,%1,%2,%3}, {%4,%5,%6,%7}, {%8,%9}, {%0,%1,%2,%3};"
        : "+f"(d[0]), "+f"(d[1]), "+f"(d[2]), "+f"(d[3])
        : "r"(a[0]), "r"(a[1]), "r"(a[2]), "r"(a[3]), "r"(b0), "r"(b1));
}
__device__ __forceinline__ void mma_f16(float* d, unsigned a0, unsigned a1,
                                        unsigned a2, unsigned a3,
                                        unsigned b0, unsigned b1) {
    asm volatile(
        "mma.sync.aligned.m16n8k16.row.col.f32.f16.f16.f32 "
        "{%0,%1,%2,%3}, {%4,%5,%6,%7}, {%8,%9}, {%0,%1,%2,%3};"
        : "+f"(d[0]), "+f"(d[1]), "+f"(d[2]), "+f"(d[3])
        : "r"(a0), "r"(a1), "r"(a2), "r"(a3), "r"(b0), "r"(b1));
}
__device__ __forceinline__ void mma_bf16(float* d, unsigned a0, unsigned a1,
                                         unsigned a2, unsigned a3,
                                         unsigned b0, unsigned b1) {
    asm volatile(
        "mma.sync.aligned.m16n8k16.row.col.f32.bf16.bf16.f32 "
        "{%0,%1,%2,%3}, {%4,%5,%6,%7}, {%8,%9}, {%0,%1,%2,%3};"
        : "+f"(d[0]), "+f"(d[1]), "+f"(d[2]), "+f"(d[3])
        : "r"(a0), "r"(a1), "r"(a2), "r"(a3), "r"(b0), "r"(b1));
}
__device__ __forceinline__ void cp16(unsigned dst, const void* src) {
    asm volatile("cp.async.cg.shared.global [%0], [%1], 16;"
                 :: "r"(dst), "l"(src));
}
#define CP_COMMIT() asm volatile("cp.async.commit_group;")
#define CP_WAIT1()  asm volatile("cp.async.wait_group 1;")

// ---------------- weight fp32 -> bf16 conversion ---------------------------
// 16 jobs of 1M elements each: z 0-3 -> wq..wo, 4-7 -> wg, 8-11 -> wh, 12-15 -> wd
__global__ void __launch_bounds__(256) cvt_w_kernel(
    const float* __restrict__ wq, const float* __restrict__ wk,
    const float* __restrict__ wv, const float* __restrict__ wo,
    const float* __restrict__ wg, const float* __restrict__ wh,
    const float* __restrict__ wd,
    __nv_bfloat16* oq, __nv_bfloat16* ok, __nv_bfloat16* ov, __nv_bfloat16* oo,
    __nv_bfloat16* og, __nv_bfloat16* oh, __nv_bfloat16* od)
{
    int z = blockIdx.y;
    const float* s;
    __nv_bfloat16* d;
    size_t off;
    if (z < 4)       { s = (z==0)?wq:(z==1)?wk:(z==2)?wv:wo;
                       d = (z==0)?oq:(z==1)?ok:(z==2)?ov:oo; off = 0; }
    else if (z < 8)  { s = wg; d = og; off = (size_t)(z - 4)  << 20; }
    else if (z < 12) { s = wh; d = oh; off = (size_t)(z - 8)  << 20; }
    else             { s = wd; d = od; off = (size_t)(z - 12) << 20; }
    size_t i = blockIdx.x * 256 + threadIdx.x;     // float4 index within 1M elems
    float4 v = ((const float4*)(s + off))[i];
    __nv_bfloat162* dp = (__nv_bfloat162*)(d + off);
    dp[i * 2]     = __floats2bfloat162_rn(v.x, v.y);
    dp[i * 2 + 1] = __floats2bfloat162_rn(v.z, v.w);
}

// ---------------- rmsnorm: fp32 in, bf16 out -------------------------------
__global__ void __launch_bounds__(256) rmsnorm_kernel(
    const float* __restrict__ x, const float* __restrict__ w,
    __nv_bfloat16* __restrict__ y)
{
    int row = blockIdx.x;
    int t   = threadIdx.x;
    const float4* xr = (const float4*)(x + (size_t)row * D_MODEL);
    float4 v = xr[t];
    float ss = v.x * v.x + v.y * v.y + v.z * v.z + v.w * v.w;
    #pragma unroll
    for (int m = 16; m; m >>= 1) ss += __shfl_xor_sync(0xffffffffu, ss, m);
    __shared__ float red[8];
    if ((t & 31) == 0) red[t >> 5] = ss;
    __syncthreads();
    float tot = 0.f;
    #pragma unroll
    for (int i = 0; i < 8; i++) tot += red[i];
    float r = rsqrtf(tot * (1.0f / D_MODEL) + 1e-6f);
    float4 wv = ((const float4*)w)[t];
    __nv_bfloat162* yr = (__nv_bfloat162*)(y + (size_t)row * D_MODEL) + t * 2;
    yr[0] = __floats2bfloat162_rn(v.x * wv.x * r, v.y * wv.y * r);
    yr[1] = __floats2bfloat162_rn(v.z * wv.z * r, v.w * wv.w * r);
}

// ---------------- bf16 tensor-core GEMM, cp.async 3-stage -------------------
// C[M,N] fp32 = A[M,K]bf16 @ B[K,N]bf16 (+bias)(+res)
// 128x128 tile, BK=32, 256 threads (8 warps 2x4), warp tile 64x32, 2 CTA/SM.
#define BMh 128
#define BNh 128
#define BKh 32
#define SAh 40      // A smem row stride in halves (32 + 8 pad) -> 80B
#define SBh 136     // B smem row stride in halves (128 + 8 pad) -> 272B
#define ASTG (BMh * SAh)     // 5120 halves / stage
#define BSTG (BKh * SBh)     // 4352 halves / stage
#define NSTG 3
#define GEMM_SMEM ((ASTG + BSTG) * NSTG * 2)   // 56832 bytes

__device__ __forceinline__ void gemm_body(
    const __nv_bfloat16* __restrict__ A, const __nv_bfloat16* __restrict__ B,
    const float* __restrict__ bias, const float* __restrict__ res,
    float* __restrict__ C, int M, int N, int K)
{
    extern __shared__ __nv_bfloat16 smh[];
    __nv_bfloat16* As = smh;
    __nv_bfloat16* Bs = smh + NSTG * ASTG;

    const int tid  = threadIdx.x;
    const int lane = tid & 31;
    const int warp = tid >> 5;
    const int wm = (warp >> 2) * 64;
    const int wn = (warp & 3) * 32;
    const int row0 = blockIdx.y * BMh;
    const int col0 = blockIdx.x * BNh;

    const unsigned as_u = smem_u32(As);
    const unsigned bs_u = smem_u32(Bs);

    // cp.async coords: A thread loads 32B (row tid/2), B thread loads 32B
    const int arow  = tid >> 1;
    const int acolh = (tid & 1) * 16;
    const int brow  = tid >> 3;
    const int bcolh = (tid & 7) * 16;
    const __nv_bfloat16* Ag = A + (size_t)(row0 + arow) * K + acolh;
    const __nv_bfloat16* Bg = B + (size_t)brow * N + col0 + bcolh;
    const unsigned adst = as_u + (arow * SAh + acolh) * 2;
    const unsigned bdst = bs_u + (brow * SBh + bcolh) * 2;

    float acc[4][4][4];
    #pragma unroll
    for (int i = 0; i < 4; i++)
        #pragma unroll
        for (int j = 0; j < 4; j++)
            #pragma unroll
            for (int r = 0; r < 4; r++) acc[i][j][r] = 0.f;

    const int KC = K / BKh;

    // prologue: stages 0,1
    #pragma unroll
    for (int s = 0; s < 2; s++) {
        const __nv_bfloat16* ag = Ag + s * BKh;
        const __nv_bfloat16* bg = Bg + (size_t)s * BKh * N;
        unsigned ad = adst + s * ASTG * 2;
        unsigned bd = bdst + s * BSTG * 2;
        cp16(ad, ag); cp16(ad + 16, ag + 8);
        cp16(bd, bg); cp16(bd + 16, bg + 8);
        CP_COMMIT();
    }

    for (int c = 0; c < KC; c++) {
        CP_WAIT1();
        __syncthreads();

        // issue loads for stage c+2 (into buffer being freed)
        if (c + 2 < KC) {
            const int s = (c + 2) % NSTG;
            const __nv_bfloat16* ag = Ag + (c + 2) * BKh;
            const __nv_bfloat16* bg = Bg + (size_t)(c + 2) * BKh * N;
            unsigned ad = adst + s * ASTG * 2;
            unsigned bd = bdst + s * BSTG * 2;
            cp16(ad, ag); cp16(ad + 16, ag + 8);
            cp16(bd, bg); cp16(bd + 16, bg + 8);
        }
        CP_COMMIT();

        const int s = c % NSTG;
        const unsigned asb = as_u + s * ASTG * 2;
        const unsigned bsb = bs_u + s * BSTG * 2;

        #pragma unroll
        for (int ks = 0; ks < 2; ks++) {
            const int k0 = ks * 16;
            unsigned a[4][4];
            #pragma unroll
            for (int mf = 0; mf < 4; mf++) {
                unsigned addr = asb +
                    ((wm + mf * 16 + (lane & 15)) * SAh + k0 + (lane >> 4) * 8) * 2;
                ldsm_x4(a[mf][0], a[mf][1], a[mf][2], a[mf][3], addr);
            }
            unsigned b[2][4];
            #pragma unroll
            for (int nb = 0; nb < 2; nb++) {
                unsigned addr = bsb +
                    ((k0 + (lane & 15)) * SBh + wn + nb * 16 + (lane >> 4) * 8) * 2;
                ldsm_x4_t(b[nb][0], b[nb][1], b[nb][2], b[nb][3], addr);
            }
            #pragma unroll
            for (int mf = 0; mf < 4; mf++)
                #pragma unroll
                for (int nf = 0; nf < 4; nf++)
                    mma_bf16(acc[mf][nf], a[mf][0], a[mf][1], a[mf][2], a[mf][3],
                             b[nf >> 1][(nf & 1) * 2], b[nf >> 1][(nf & 1) * 2 + 1]);
        }
    }

    // epilogue
    #pragma unroll
    for (int mf = 0; mf < 4; mf++) {
        const int r = row0 + wm + mf * 16 + (lane >> 2);
        #pragma unroll
        for (int nf = 0; nf < 4; nf++) {
            const int cc = col0 + wn + nf * 8 + (lane & 3) * 2;
            float2 v0 = make_float2(acc[mf][nf][0], acc[mf][nf][1]);
            float2 v1 = make_float2(acc[mf][nf][2], acc[mf][nf][3]);
            if (bias) {
                float2 bv = *(const float2*)(bias + cc);
                v0.x += bv.x; v0.y += bv.y;
                v1.x += bv.x; v1.y += bv.y;
            }
            if (res) {
                float2 r0 = *(const float2*)(res + (size_t)r * N + cc);
                float2 r1 = *(const float2*)(res + (size_t)(r + 8) * N + cc);
                v0.x += r0.x; v0.y += r0.y;
                v1.x += r1.x; v1.y += r1.y;
            }
            *(float2*)(C + (size_t)r * N + cc) = v0;
            *(float2*)(C + (size_t)(r + 8) * N + cc) = v1;
        }
    }
}

__global__ void __launch_bounds__(256, 2) mma_gemm_kernel(
    const __nv_bfloat16* __restrict__ A, const __nv_bfloat16* __restrict__ B,
    const float* __restrict__ bias, const float* __restrict__ res,
    float* __restrict__ C, int M, int N, int K)
{
    gemm_body(A, B, bias, res, C, M, N, K);
}

__global__ void __launch_bounds__(256, 2) mma_gemm_multi(
    const __nv_bfloat16* __restrict__ A,
    const __nv_bfloat16* __restrict__ B0, const __nv_bfloat16* __restrict__ B1,
    const __nv_bfloat16* __restrict__ B2,
    float* __restrict__ C0, float* __restrict__ C1, float* __restrict__ C2,
    int M, int N, int K)
{
    const __nv_bfloat16* B = (blockIdx.z == 0) ? B0 : (blockIdx.z == 1) ? B1 : B2;
    float*               C = (blockIdx.z == 0) ? C0 : (blockIdx.z == 1) ? C1 : C2;
    gemm_body(A, B, nullptr, nullptr, C, M, N, K);
}

// ---------------- flash attention v2 (unchanged math; bf16 output) ---------
#define AQS 68
#define AVS 72
#define FL_SMEM (2 * 64 * AQS * 4 + 2 * 64 * AVS * 2)

__global__ void __launch_bounds__(256) flash2_kernel(
    const float* __restrict__ Q, const float* __restrict__ Kg,
    const float* __restrict__ Vg, __nv_bfloat16* __restrict__ O)
{
    extern __shared__ char fsm[];
    float*  Kf = (float*)fsm;
    __half* Vh = (__half*)(fsm + 2 * 64 * AQS * 4);

    const int tid  = threadIdx.x;
    const int lane = tid & 31;
    const int warp = tid >> 5;
    const int bq = blockIdx.x, head = blockIdx.y, b = blockIdx.z;
    const size_t qtok0 = (size_t)b * SEQ + (size_t)bq * 128;
    const size_t ktokb = (size_t)b * SEQ;
    const int col0 = head * HD;
    const int m0 = warp * 16;
    const float QSCALE = 0.125f * 1.4426950408889634f;

    const unsigned kf_u32 = smem_u32(Kf);
    const unsigned vh_u32 = smem_u32(Vh);

    #pragma unroll
    for (int j = 0; j < 8; j++) {
        int f = tid + j * 256;
        int r = f >> 4, c = (f & 15) * 4;
        float4 v = *(const float4*)(Q + (qtok0 + r) * D_MODEL + col0 + c);
        float4 t;
        t.x = __uint_as_float(f2tf(v.x * QSCALE));
        t.y = __uint_as_float(f2tf(v.y * QSCALE));
        t.z = __uint_as_float(f2tf(v.z * QSCALE));
        t.w = __uint_as_float(f2tf(v.w * QSCALE));
        *(float4*)(Kf + r * AQS + c) = t;
    }
    __syncthreads();

    unsigned qa[8][4];
    #pragma unroll
    for (int k0 = 0; k0 < 8; k0++) {
        unsigned addr = kf_u32 +
            ((m0 + (lane & 15)) * AQS + k0 * 8 + (lane >> 4) * 4) * 4;
        ldsm_x4(qa[k0][0], qa[k0][1], qa[k0][2], qa[k0][3], addr);
    }
    __syncthreads();

    #pragma unroll
    for (int j = 0; j < 4; j++) {
        int f = tid + j * 256;
        int r = f >> 4, c = (f & 15) * 4;
        float4 kv4 = *(const float4*)(Kg + (ktokb + r) * D_MODEL + col0 + c);
        float4 vv4 = *(const float4*)(Vg + (ktokb + r) * D_MODEL + col0 + c);
        float4 t;
        t.x = __uint_as_float(f2tf(kv4.x)); t.y = __uint_as_float(f2tf(kv4.y));
        t.z = __uint_as_float(f2tf(kv4.z)); t.w = __uint_as_float(f2tf(kv4.w));
        *(float4*)(Kf + r * AQS + c) = t;
        *(__half2*)(Vh + r * AVS + c)     = __floats2half2_rn(vv4.x, vv4.y);
        *(__half2*)(Vh + r * AVS + c + 2) = __floats2half2_rn(vv4.z, vv4.w);
    }
    __syncthreads();

    float m0s = -INFINITY, m1s = -INFINITY, l0s = 0.f, l1s = 0.f;
    float oacc[8][4];
    #pragma unroll
    for (int i = 0; i < 8; i++)
        #pragma unroll
        for (int j = 0; j < 4; j++) oacc[i][j] = 0.f;

    for (int kvt = 0; kvt < SEQ / 64; kvt++) {
        const int buf = kvt & 1;
        const bool pre = (kvt + 1) < SEQ / 64;
        float4 kr[4], vr[4];
        if (pre) {
            size_t kt = ktokb + (size_t)(kvt + 1) * 64;
            #pragma unroll
            for (int j = 0; j < 4; j++) {
                int f = tid + j * 256;
                int r = f >> 4, c = (f & 15) * 4;
                kr[j] = *(const float4*)(Kg + (kt + r) * D_MODEL + col0 + c);
                vr[j] = *(const float4*)(Vg + (kt + r) * D_MODEL + col0 + c);
            }
        }

        float sacc[8][4];
        #pragma unroll
        for (int i = 0; i < 8; i++)
            #pragma unroll
            for (int j = 0; j < 4; j++) sacc[i][j] = 0.f;

        const unsigned kfb = kf_u32 + buf * 64 * AQS * 4;
        #pragma unroll
        for (int k0 = 0; k0 < 8; k0++) {
            #pragma unroll
            for (int nf2 = 0; nf2 < 4; nf2++) {
                const int midx = lane >> 3;
                unsigned addr = kfb +
                    ((nf2 * 16 + (midx >> 1) * 8 + (lane & 7)) * AQS +
                     k0 * 8 + (midx & 1) * 4) * 4;
                unsigned b0, b1, b2, b3;
                ldsm_x4(b0, b1, b2, b3, addr);
                mma_tf32(sacc[nf2 * 2],     qa[k0], b0, b1);
                mma_tf32(sacc[nf2 * 2 + 1], qa[k0], b2, b3);
            }
        }

        float mx0 = -INFINITY, mx1 = -INFINITY;
        #pragma unroll
        for (int nf = 0; nf < 8; nf++) {
            mx0 = fmaxf(mx0, fmaxf(sacc[nf][0], sacc[nf][1]));
            mx1 = fmaxf(mx1, fmaxf(sacc[nf][2], sacc[nf][3]));
        }
        mx0 = fmaxf(mx0, __shfl_xor_sync(0xffffffffu, mx0, 1));
        mx0 = fmaxf(mx0, __shfl_xor_sync(0xffffffffu, mx0, 2));
        mx1 = fmaxf(mx1, __shfl_xor_sync(0xffffffffu, mx1, 1));
        mx1 = fmaxf(mx1, __shfl_xor_sync(0xffffffffu, mx1, 2));

        const float mn0 = fmaxf(m0s, mx0);
        const float mn1 = fmaxf(m1s, mx1);
        const float al0 = ex2f(m0s - mn0);
        const float al1 = ex2f(m1s - mn1);

        unsigned pa0[8], pa1[8];
        float ls0 = 0.f, ls1 = 0.f;
        #pragma unroll
        for (int nf = 0; nf < 8; nf++) {
            float p0 = ex2f(sacc[nf][0] - mn0);
            float p1 = ex2f(sacc[nf][1] - mn0);
            float p2 = ex2f(sacc[nf][2] - mn1);
            float p3 = ex2f(sacc[nf][3] - mn1);
            ls0 += p0 + p1;
            ls1 += p2 + p3;
            pa0[nf] = packh2(p0, p1);
            pa1[nf] = packh2(p2, p3);
        }
        ls0 += __shfl_xor_sync(0xffffffffu, ls0, 1);
        ls0 += __shfl_xor_sync(0xffffffffu, ls0, 2);
        ls1 += __shfl_xor_sync(0xffffffffu, ls1, 1);
        ls1 += __shfl_xor_sync(0xffffffffu, ls1, 2);
        l0s = l0s * al0 + ls0;
        l1s = l1s * al1 + ls1;
        m0s = mn0; m1s = mn1;

        #pragma unroll
        for (int nf = 0; nf < 8; nf++) {
            oacc[nf][0] *= al0; oacc[nf][1] *= al0;
            oacc[nf][2] *= al1; oacc[nf][3] *= al1;
        }

        const unsigned vhb = vh_u32 + buf * 64 * AVS * 2;
        #pragma unroll
        for (int ks = 0; ks < 4; ks++) {
            unsigned a0 = pa0[2 * ks],     a1 = pa1[2 * ks];
            unsigned a2 = pa0[2 * ks + 1], a3 = pa1[2 * ks + 1];
            #pragma unroll
            for (int no = 0; no < 4; no++) {
                unsigned addr = vhb +
                    ((ks * 16 + (lane & 15)) * AVS + no * 16 + (lane >> 4) * 8) * 2;
                unsigned b0, b1, b2, b3;
                ldsm_x4_t(b0, b1, b2, b3, addr);
                mma_f16(oacc[no * 2],     a0, a1, a2, a3, b0, b1);
                mma_f16(oacc[no * 2 + 1], a0, a1, a2, a3, b2, b3);
            }
        }

        if (pre) {
            float*  Kfd = Kf + (buf ^ 1) * 64 * AQS;
            __half* Vhd = Vh + (buf ^ 1) * 64 * AVS;
            #pragma unroll
            for (int j = 0; j < 4; j++) {
                int f = tid + j * 256;
                int r = f >> 4, c = (f & 15) * 4;
                float4 t;
                t.x = __uint_as_float(f2tf(kr[j].x)); t.y = __uint_as_float(f2tf(kr[j].y));
                t.z = __uint_as_float(f2tf(kr[j].z)); t.w = __uint_as_float(f2tf(kr[j].w));
                *(float4*)(Kfd + r * AQS + c) = t;
                *(__half2*)(Vhd + r * AVS + c)     = __floats2half2_rn(vr[j].x, vr[j].y);
                *(__half2*)(Vhd + r * AVS + c + 2) = __floats2half2_rn(vr[j].z, vr[j].w);
            }
        }
        __syncthreads();
    }

    const float i0 = 1.f / l0s;
    const float i1 = 1.f / l1s;
    const size_t row0 = qtok0 + m0 + (lane >> 2);
    #pragma unroll
    for (int no = 0; no < 8; no++) {
        const int cw = col0 + no * 8 + (lane & 3) * 2;
        *(__nv_bfloat162*)(O + row0 * D_MODEL + cw) =
            __floats2bfloat162_rn(oacc[no][0] * i0, oacc[no][1] * i0);
        *(__nv_bfloat162*)(O + (row0 + 8) * D_MODEL + cw) =
            __floats2bfloat162_rn(oacc[no][2] * i1, oacc[no][3] * i1);
    }
}

// ---------------- silu(h1) * h2 -> bf16 ------------------------------------
__global__ void __launch_bounds__(256) silu_mul_kernel(
    const float* __restrict__ h1, const float* __restrict__ h2,
    __nv_bfloat16* __restrict__ hb, int n4)
{
    int i = blockIdx.x * blockDim.x + threadIdx.x;
    if (i < n4) {
        float4 a = ((const float4*)h1)[i];
        float4 c = ((const float4*)h2)[i];
        a.x = a.x / (1.f + __expf(-a.x)) * c.x;
        a.y = a.y / (1.f + __expf(-a.y)) * c.y;
        a.z = a.z / (1.f + __expf(-a.z)) * c.z;
        a.w = a.w / (1.f + __expf(-a.w)) * c.w;
        __nv_bfloat162* o = (__nv_bfloat162*)hb + i * 2;
        o[0] = __floats2bfloat162_rn(a.x, a.y);
        o[1] = __floats2bfloat162_rn(a.z, a.w);
    }
}

// ---------------- driver ----------------------------------------------------
extern "C" void kernel_launch(void* const* d_in, const int* in_sizes, int n_in,
                              void* d_out, int out_size)
{
    const float* x       = (const float*)d_in[0];
    const float* W_q     = (const float*)d_in[1];
    const float* W_k     = (const float*)d_in[2];
    const float* W_v     = (const float*)d_in[3];
    const float* W_o     = (const float*)d_in[4];
    const float* b_o     = (const float*)d_in[5];
    const float* a_nw    = (const float*)d_in[6];
    const float* f_nw    = (const float*)d_in[7];
    const float* W_gate  = (const float*)d_in[8];
    const float* W_hid   = (const float*)d_in[9];
    const float* W_out   = (const float*)d_in[10];
    const float* b_out   = (const float*)d_in[11];
    float* out = (float*)d_out;

    float *q, *k, *v, *x1, *h1, *h2;
    __nv_bfloat16 *xnb, *atb, *hb, *wq, *wk, *wv, *wo, *wg, *wh, *wd;
    cudaGetSymbolAddress((void**)&q,   g_q);
    cudaGetSymbolAddress((void**)&k,   g_k);
    cudaGetSymbolAddress((void**)&v,   g_v);
    cudaGetSymbolAddress((void**)&x1,  g_x1);
    cudaGetSymbolAddress((void**)&h1,  g_h1);
    cudaGetSymbolAddress((void**)&h2,  g_h2);
    cudaGetSymbolAddress((void**)&xnb, g_xnb);
    cudaGetSymbolAddress((void**)&atb, g_atb);
    cudaGetSymbolAddress((void**)&hb,  g_hb);
    cudaGetSymbolAddress((void**)&wq,  g_wq);
    cudaGetSymbolAddress((void**)&wk,  g_wk);
    cudaGetSymbolAddress((void**)&wv,  g_wv);
    cudaGetSymbolAddress((void**)&wo,  g_wo);
    cudaGetSymbolAddress((void**)&wg,  g_wg);
    cudaGetSymbolAddress((void**)&wh,  g_wh);
    cudaGetSymbolAddress((void**)&wd,  g_wd);

    cudaFuncSetAttribute(flash2_kernel,
                         cudaFuncAttributeMaxDynamicSharedMemorySize, FL_SMEM);
    cudaFuncSetAttribute(mma_gemm_kernel,
                         cudaFuncAttributeMaxDynamicSharedMemorySize, GEMM_SMEM);
    cudaFuncSetAttribute(mma_gemm_multi,
                         cudaFuncAttributeMaxDynamicSharedMemorySize, GEMM_SMEM);

    // 0) convert weights to bf16 (16 x 1M-element jobs)
    dim3 gc(1024, 16);
    cvt_w_kernel<<<gc, 256>>>(W_q, W_k, W_v, W_o, W_gate, W_hid, W_out,
                              wq, wk, wv, wo, wg, wh, wd);

    // 1) attn rmsnorm -> bf16
    rmsnorm_kernel<<<N_TOK, 256>>>(x, a_nw, xnb);

    // 2) q, k, v projections (batched)
    dim3 gqkv(D_MODEL / BNh, N_TOK / BMh, 3);
    mma_gemm_multi<<<gqkv, 256, GEMM_SMEM>>>(xnb, wq, wk, wv, q, k, v,
                                             N_TOK, D_MODEL, D_MODEL);

    // 3) attention -> bf16
    dim3 ga(SEQ / 128, N_HEADS, 2);
    flash2_kernel<<<ga, 256, FL_SMEM>>>(q, k, v, atb);

    // 4) output projection + bias + residual
    dim3 gd(D_MODEL / BNh, N_TOK / BMh);
    mma_gemm_kernel<<<gd, 256, GEMM_SMEM>>>(atb, wo, b_o, x, x1,
                                            N_TOK, D_MODEL, D_MODEL);

    // 5) ffn rmsnorm -> bf16
    rmsnorm_kernel<<<N_TOK, 256>>>(x1, f_nw, xnb);

    // 6) gate / hidden projections (batched)
    dim3 gf(D_FF / BNh, N_TOK / BMh, 2);
    mma_gemm_multi<<<gf, 256, GEMM_SMEM>>>(xnb, wg, wh, wh, h1, h2, h2,
                                           N_TOK, D_FF, D_MODEL);

    // 7) silu(gate) * hidden -> bf16
    int n4 = N_TOK * D_FF / 4;
    silu_mul_kernel<<<(n4 + 255) / 256, 256>>>(h1, h2, hb, n4);

    // 8) down projection + bias + residual -> out
    mma_gemm_kernel<<<gd, 256, GEMM_SMEM>>>(hb, wd, b_out, x1, out,
                                            N_TOK, D_MODEL, D_FF);
}

// round 6
// speedup vs baseline: 6.3641x; 1.0467x over previous
#include <cuda_runtime.h>
#include <cuda_fp16.h>
#include <cuda_bf16.h>
#include <math.h>

#define D_MODEL 1024
#define N_TOK   4096
#define N_HEADS 16
#define HD      64
#define D_FF    4096
#define SEQ     2048

// ---------------- scratch (device globals; no allocation allowed) ----------
__device__ float g_q [N_TOK * D_MODEL];
__device__ float g_k [N_TOK * D_MODEL];
__device__ float g_v [N_TOK * D_MODEL];
__device__ float g_x1[N_TOK * D_MODEL];
__device__ __nv_bfloat16 g_xnb[N_TOK * D_MODEL];
__device__ __nv_bfloat16 g_atb[N_TOK * D_MODEL];
__device__ __nv_bfloat16 g_hb [N_TOK * D_FF];
// bf16 weights, [K, N] layout (as given)
__device__ __nv_bfloat16 g_wq[D_MODEL * D_MODEL];
__device__ __nv_bfloat16 g_wk[D_MODEL * D_MODEL];
__device__ __nv_bfloat16 g_wv[D_MODEL * D_MODEL];
__device__ __nv_bfloat16 g_wo[D_MODEL * D_MODEL];
__device__ __nv_bfloat16 g_wg[D_MODEL * D_FF];
__device__ __nv_bfloat16 g_wh[D_MODEL * D_FF];
__device__ __nv_bfloat16 g_wd[D_FF * D_MODEL];

// ---------------- helpers ---------------------------------------------------
__device__ __forceinline__ unsigned smem_u32(const void* p) {
    unsigned a;
    asm("{ .reg .u64 t; cvta.to.shared.u64 t, %1; cvt.u32.u64 %0, t; }"
        : "=r"(a) : "l"(p));
    return a;
}
__device__ __forceinline__ unsigned f2tf(float x) {
    unsigned r;
    asm("cvt.rna.tf32.f32 %0, %1;" : "=r"(r) : "f"(x));
    return r;
}
__device__ __forceinline__ float ex2f(float x) {
    float y;
    asm("ex2.approx.ftz.f32 %0, %1;" : "=f"(y) : "f"(x));
    return y;
}
__device__ __forceinline__ unsigned packh2(float lo, float hi) {
    unsigned d;
    asm("cvt.rn.f16x2.f32 %0, %1, %2;" : "=r"(d) : "f"(hi), "f"(lo));
    return d;
}
__device__ __forceinline__ void ldsm_x4(unsigned& r0, unsigned& r1,
                                        unsigned& r2, unsigned& r3, unsigned addr) {
    asm volatile("ldmatrix.sync.aligned.m8n8.x4.shared.b16 {%0,%1,%2,%3}, [%4];"
                 : "=r"(r0), "=r"(r1), "=r"(r2), "=r"(r3) : "r"(addr));
}
__device__ __forceinline__ void ldsm_x4_t(unsigned& r0, unsigned& r1,
                                          unsigned& r2, unsigned& r3, unsigned addr) {
    asm volatile("ldmatrix.sync.aligned.m8n8.x4.trans.shared.b16 {%0,%1,%2,%3}, [%4];"
                 : "=r"(r0), "=r"(r1), "=r"(r2), "=r"(r3) : "r"(addr));
}
__device__ __forceinline__ void mma_tf32(float* d, const unsigned* a,
                                         unsigned b0, unsigned b1) {
    asm volatile(
        "mma.sync.aligned.m16n8k8.row.col.f32.tf32.tf32.f32 "
        "{%0,%1,%2,%3}, {%4,%5,%6,%7}, {%8,%9}, {%0,%1,%2,%3};"
        : "+f"(d[0]), "+f"(d[1]), "+f"(d[2]), "+f"(d[3])
        : "r"(a[0]), "r"(a[1]), "r"(a[2]), "r"(a[3]), "r"(b0), "r"(b1));
}
__device__ __forceinline__ void mma_f16(float* d, unsigned a0, unsigned a1,
                                        unsigned a2, unsigned a3,
                                        unsigned b0, unsigned b1) {
    asm volatile(
        "mma.sync.aligned.m16n8k16.row.col.f32.f16.f16.f32 "
        "{%0,%1,%2,%3}, {%4,%5,%6,%7}, {%8,%9}, {%0,%1,%2,%3};"
        : "+f"(d[0]), "+f"(d[1]), "+f"(d[2]), "+f"(d[3])
        : "r"(a0), "r"(a1), "r"(a2), "r"(a3), "r"(b0), "r"(b1));
}
__device__ __forceinline__ void mma_bf16(float* d, unsigned a0, unsigned a1,
                                         unsigned a2, unsigned a3,
                                         unsigned b0, unsigned b1) {
    asm volatile(
        "mma.sync.aligned.m16n8k16.row.col.f32.bf16.bf16.f32 "
        "{%0,%1,%2,%3}, {%4,%5,%6,%7}, {%8,%9}, {%0,%1,%2,%3};"
        : "+f"(d[0]), "+f"(d[1]), "+f"(d[2]), "+f"(d[3])
        : "r"(a0), "r"(a1), "r"(a2), "r"(a3), "r"(b0), "r"(b1));
}
__device__ __forceinline__ void cp16(unsigned dst, const void* src) {
    asm volatile("cp.async.cg.shared.global [%0], [%1], 16;"
                 :: "r"(dst), "l"(src));
}
#define CP_COMMIT() asm volatile("cp.async.commit_group;")
#define CP_WAIT0()  asm volatile("cp.async.wait_group 0;")

// ---------------- weight fp32 -> bf16 conversion (keeps [K,N]) -------------
__global__ void __launch_bounds__(256) cvt_w_kernel(
    const float* __restrict__ wq, const float* __restrict__ wk,
    const float* __restrict__ wv, const float* __restrict__ wo,
    const float* __restrict__ wg, const float* __restrict__ wh,
    const float* __restrict__ wd,
    __nv_bfloat16* oq, __nv_bfloat16* ok, __nv_bfloat16* ov, __nv_bfloat16* oo,
    __nv_bfloat16* og, __nv_bfloat16* oh, __nv_bfloat16* od)
{
    int z = blockIdx.y;
    const float* s;
    __nv_bfloat16* d;
    size_t off;
    if (z < 4)       { s = (z==0)?wq:(z==1)?wk:(z==2)?wv:wo;
                       d = (z==0)?oq:(z==1)?ok:(z==2)?ov:oo; off = 0; }
    else if (z < 8)  { s = wg; d = og; off = (size_t)(z - 4)  << 20; }
    else if (z < 12) { s = wh; d = oh; off = (size_t)(z - 8)  << 20; }
    else             { s = wd; d = od; off = (size_t)(z - 12) << 20; }
    size_t i = blockIdx.x * 256 + threadIdx.x;
    float4 v = ((const float4*)(s + off))[i];
    __nv_bfloat162* dp = (__nv_bfloat162*)(d + off);
    dp[i * 2]     = __floats2bfloat162_rn(v.x, v.y);
    dp[i * 2 + 1] = __floats2bfloat162_rn(v.z, v.w);
}

// ---------------- rmsnorm: fp32 in, bf16 out -------------------------------
__global__ void __launch_bounds__(256) rmsnorm_kernel(
    const float* __restrict__ x, const float* __restrict__ w,
    __nv_bfloat16* __restrict__ y)
{
    int row = blockIdx.x;
    int t   = threadIdx.x;
    const float4* xr = (const float4*)(x + (size_t)row * D_MODEL);
    float4 v = xr[t];
    float ss = v.x * v.x + v.y * v.y + v.z * v.z + v.w * v.w;
    #pragma unroll
    for (int m = 16; m; m >>= 1) ss += __shfl_xor_sync(0xffffffffu, ss, m);
    __shared__ float red[8];
    if ((t & 31) == 0) red[t >> 5] = ss;
    __syncthreads();
    float tot = 0.f;
    #pragma unroll
    for (int i = 0; i < 8; i++) tot += red[i];
    float r = rsqrtf(tot * (1.0f / D_MODEL) + 1e-6f);
    float4 wv = ((const float4*)w)[t];
    __nv_bfloat162* yr = (__nv_bfloat162*)(y + (size_t)row * D_MODEL) + t * 2;
    yr[0] = __floats2bfloat162_rn(v.x * wv.x * r, v.y * wv.y * r);
    yr[1] = __floats2bfloat162_rn(v.z * wv.z * r, v.w * wv.w * r);
}

// ---------------- bf16 HMMA GEMM core: multi-stage cp.async ----------------
#define BKh 32
#define SAh 40      // A smem row stride (halves)
#define SBh 136     // B smem row stride (halves)
#define ASTG (128 * SAh)    // 5120 halves
#define BSTG (BKh * SBh)    // 4352 halves
#define STG_B ((ASTG + BSTG) * 2)      // 18944 bytes per stage
#define G5_SMEM (5 * STG_B)            // 94720
#define SWI_STASH (256 * 33 * 4)       // 33792
#define SWI_SMEM (4 * STG_B + SWI_STASH)  // 109568

// K-loop: acc += A[row0:128, :] @ B[:, col0:128]; A bf16 [M,K], B bf16 [K,N]
template<int NSTG>
__device__ __forceinline__ void gemm_kloop(
    const __nv_bfloat16* __restrict__ Ab,   // A + row0*K
    const __nv_bfloat16* __restrict__ Bb,   // B + col0
    int N, int K, unsigned as_u, unsigned bs_u,
    float (&acc)[4][4][4], int tid, int lane, int wm, int wn)
{
    const int arow = tid >> 1, acolh = (tid & 1) * 16;
    const int brow = tid >> 3, bcolh = (tid & 7) * 16;
    const __nv_bfloat16* Ag = Ab + (size_t)arow * K + acolh;
    const __nv_bfloat16* Bg = Bb + (size_t)brow * N + bcolh;
    const unsigned adst = as_u + (arow * SAh + acolh) * 2;
    const unsigned bdst = bs_u + (brow * SBh + bcolh) * 2;
    const int KC = K / BKh;

    #pragma unroll
    for (int s = 0; s < NSTG - 1; s++) {
        const __nv_bfloat16* ag = Ag + s * BKh;
        const __nv_bfloat16* bg = Bg + (size_t)s * BKh * N;
        cp16(adst + s * ASTG * 2, ag);
        cp16(adst + s * ASTG * 2 + 16, ag + 8);
        cp16(bdst + s * BSTG * 2, bg);
        cp16(bdst + s * BSTG * 2 + 16, bg + 8);
        CP_COMMIT();
    }

    for (int c = 0; c < KC; c++) {
        asm volatile("cp.async.wait_group %0;" :: "n"(NSTG - 2));
        __syncthreads();

        if (c + NSTG - 1 < KC) {
            const int s = (c + NSTG - 1) % NSTG;
            const __nv_bfloat16* ag = Ag + (c + NSTG - 1) * BKh;
            const __nv_bfloat16* bg = Bg + (size_t)(c + NSTG - 1) * BKh * N;
            cp16(adst + s * ASTG * 2, ag);
            cp16(adst + s * ASTG * 2 + 16, ag + 8);
            cp16(bdst + s * BSTG * 2, bg);
            cp16(bdst + s * BSTG * 2 + 16, bg + 8);
        }
        CP_COMMIT();

        const int s = c % NSTG;
        const unsigned asb = as_u + s * ASTG * 2;
        const unsigned bsb = bs_u + s * BSTG * 2;
        #pragma unroll
        for (int ks = 0; ks < 2; ks++) {
            const int k0 = ks * 16;
            unsigned a[4][4];
            #pragma unroll
            for (int mf = 0; mf < 4; mf++) {
                unsigned addr = asb +
                    ((wm + mf * 16 + (lane & 15)) * SAh + k0 + (lane >> 4) * 8) * 2;
                ldsm_x4(a[mf][0], a[mf][1], a[mf][2], a[mf][3], addr);
            }
            unsigned b[2][4];
            #pragma unroll
            for (int nb = 0; nb < 2; nb++) {
                unsigned addr = bsb +
                    ((k0 + (lane & 15)) * SBh + wn + nb * 16 + (lane >> 4) * 8) * 2;
                ldsm_x4_t(b[nb][0], b[nb][1], b[nb][2], b[nb][3], addr);
            }
            #pragma unroll
            for (int mf = 0; mf < 4; mf++)
                #pragma unroll
                for (int nf = 0; nf < 4; nf++)
                    mma_bf16(acc[mf][nf], a[mf][0], a[mf][1], a[mf][2], a[mf][3],
                             b[nf >> 1][(nf & 1) * 2], b[nf >> 1][(nf & 1) * 2 + 1]);
        }
    }
}

__device__ __forceinline__ void gemm_epilogue(
    float (&acc)[4][4][4], const float* bias, const float* res,
    float* C, int N, int row0, int col0, int lane, int wm, int wn)
{
    #pragma unroll
    for (int mf = 0; mf < 4; mf++) {
        const int r = row0 + wm + mf * 16 + (lane >> 2);
        #pragma unroll
        for (int nf = 0; nf < 4; nf++) {
            const int cc = col0 + wn + nf * 8 + (lane & 3) * 2;
            float2 v0 = make_float2(acc[mf][nf][0], acc[mf][nf][1]);
            float2 v1 = make_float2(acc[mf][nf][2], acc[mf][nf][3]);
            if (bias) {
                float2 bv = *(const float2*)(bias + cc);
                v0.x += bv.x; v0.y += bv.y;
                v1.x += bv.x; v1.y += bv.y;
            }
            if (res) {
                float2 r0 = *(const float2*)(res + (size_t)r * N + cc);
                float2 r1 = *(const float2*)(res + (size_t)(r + 8) * N + cc);
                v0.x += r0.x; v0.y += r0.y;
                v1.x += r1.x; v1.y += r1.y;
            }
            *(float2*)(C + (size_t)r * N + cc) = v0;
            *(float2*)(C + (size_t)(r + 8) * N + cc) = v1;
        }
    }
}

__global__ void __launch_bounds__(256, 2) mma_gemm_kernel(
    const __nv_bfloat16* __restrict__ A, const __nv_bfloat16* __restrict__ B,
    const float* __restrict__ bias, const float* __restrict__ res,
    float* __restrict__ C, int M, int N, int K)
{
    extern __shared__ __nv_bfloat16 smh[];
    const unsigned as_u = smem_u32(smh);
    const int tid = threadIdx.x, lane = tid & 31, warp = tid >> 5;
    const int wm = (warp >> 2) * 64, wn = (warp & 3) * 32;
    const int row0 = blockIdx.y * 128, col0 = blockIdx.x * 128;
    float acc[4][4][4];
    #pragma unroll
    for (int i = 0; i < 4; i++)
        #pragma unroll
        for (int j = 0; j < 4; j++)
            #pragma unroll
            for (int r = 0; r < 4; r++) acc[i][j][r] = 0.f;
    gemm_kloop<5>(A + (size_t)row0 * K, B + col0, N, K,
                  as_u, as_u + 5 * ASTG * 2, acc, tid, lane, wm, wn);
    gemm_epilogue(acc, bias, res, C, N, row0, col0, lane, wm, wn);
}

__global__ void __launch_bounds__(256, 2) mma_gemm_multi(
    const __nv_bfloat16* __restrict__ A,
    const __nv_bfloat16* __restrict__ B0, const __nv_bfloat16* __restrict__ B1,
    const __nv_bfloat16* __restrict__ B2,
    float* __restrict__ C0, float* __restrict__ C1, float* __restrict__ C2,
    int M, int N, int K)
{
    extern __shared__ __nv_bfloat16 smh[];
    const unsigned as_u = smem_u32(smh);
    const __nv_bfloat16* B = (blockIdx.z == 0) ? B0 : (blockIdx.z == 1) ? B1 : B2;
    float*               C = (blockIdx.z == 0) ? C0 : (blockIdx.z == 1) ? C1 : C2;
    const int tid = threadIdx.x, lane = tid & 31, warp = tid >> 5;
    const int wm = (warp >> 2) * 64, wn = (warp & 3) * 32;
    const int row0 = blockIdx.y * 128, col0 = blockIdx.x * 128;
    float acc[4][4][4];
    #pragma unroll
    for (int i = 0; i < 4; i++)
        #pragma unroll
        for (int j = 0; j < 4; j++)
            #pragma unroll
            for (int r = 0; r < 4; r++) acc[i][j][r] = 0.f;
    gemm_kloop<5>(A + (size_t)row0 * K, B + col0, N, K,
                  as_u, as_u + 5 * ASTG * 2, acc, tid, lane, wm, wn);
    gemm_epilogue(acc, nullptr, nullptr, C, N, row0, col0, lane, wm, wn);
}

// ---------------- fused SwiGLU GEMM: hb = bf16(silu(A@Wg) * (A@Wh)) --------
__global__ void __launch_bounds__(256, 2) swiglu_gemm_kernel(
    const __nv_bfloat16* __restrict__ A,
    const __nv_bfloat16* __restrict__ Wg, const __nv_bfloat16* __restrict__ Wh,
    __nv_bfloat16* __restrict__ hb, int M, int N, int K)
{
    extern __shared__ __nv_bfloat16 smh[];
    const unsigned as_u = smem_u32(smh);
    const unsigned bs_u = as_u + 4 * ASTG * 2;
    unsigned* stash = (unsigned*)((char*)smh + 4 * STG_B);

    const int tid = threadIdx.x, lane = tid & 31, warp = tid >> 5;
    const int wm = (warp >> 2) * 64, wn = (warp & 3) * 32;
    const int row0 = blockIdx.y * 128, col0 = blockIdx.x * 128;

    float acc[4][4][4];
    #pragma unroll
    for (int i = 0; i < 4; i++)
        #pragma unroll
        for (int j = 0; j < 4; j++)
            #pragma unroll
            for (int r = 0; r < 4; r++) acc[i][j][r] = 0.f;

    // pass 1: gate
    gemm_kloop<4>(A + (size_t)row0 * K, Wg + col0, N, K,
                  as_u, bs_u, acc, tid, lane, wm, wn);

    // silu + pack to bf16, stash in smem (thread-private, stride 33)
    unsigned* st = stash + tid * 33;
    #pragma unroll
    for (int mf = 0; mf < 4; mf++)
        #pragma unroll
        for (int nf = 0; nf < 4; nf++) {
            float s0 = acc[mf][nf][0]; s0 = s0 / (1.f + __expf(-s0));
            float s1 = acc[mf][nf][1]; s1 = s1 / (1.f + __expf(-s1));
            float s2 = acc[mf][nf][2]; s2 = s2 / (1.f + __expf(-s2));
            float s3 = acc[mf][nf][3]; s3 = s3 / (1.f + __expf(-s3));
            __nv_bfloat162 p0 = __floats2bfloat162_rn(s0, s1);
            __nv_bfloat162 p1 = __floats2bfloat162_rn(s2, s3);
            st[mf * 8 + nf * 2]     = *(unsigned*)&p0;
            st[mf * 8 + nf * 2 + 1] = *(unsigned*)&p1;
        }

    __syncthreads();   // all warps done with pass-1 smem stages

    #pragma unroll
    for (int i = 0; i < 4; i++)
        #pragma unroll
        for (int j = 0; j < 4; j++)
            #pragma unroll
            for (int r = 0; r < 4; r++) acc[i][j][r] = 0.f;

    // pass 2: hidden
    gemm_kloop<4>(A + (size_t)row0 * K, Wh + col0, N, K,
                  as_u, bs_u, acc, tid, lane, wm, wn);

    // epilogue: hb = silu1 * acc2 (bf16)
    #pragma unroll
    for (int mf = 0; mf < 4; mf++) {
        const int r = row0 + wm + mf * 16 + (lane >> 2);
        #pragma unroll
        for (int nf = 0; nf < 4; nf++) {
            const int cc = col0 + wn + nf * 8 + (lane & 3) * 2;
            unsigned p0 = st[mf * 8 + nf * 2];
            unsigned p1 = st[mf * 8 + nf * 2 + 1];
            float g0 = __uint_as_float(p0 << 16);
            float g1 = __uint_as_float(p0 & 0xffff0000u);
            float g2 = __uint_as_float(p1 << 16);
            float g3 = __uint_as_float(p1 & 0xffff0000u);
            *(__nv_bfloat162*)(hb + (size_t)r * N + cc) =
                __floats2bfloat162_rn(g0 * acc[mf][nf][0], g1 * acc[mf][nf][1]);
            *(__nv_bfloat162*)(hb + (size_t)(r + 8) * N + cc) =
                __floats2bfloat162_rn(g2 * acc[mf][nf][2], g3 * acc[mf][nf][3]);
        }
    }
}

// ---------------- flash attention v3: resident Q, cp.async K, 2 CTA/SM -----
#define AQS 68   // Q/K tile row stride (floats)
#define AVS 72   // V tile row stride (halves)
#define FLQ_B (128 * AQS * 4)                 // 34816
#define FLK_B (64 * AQS * 4)                  // 17408 per buffer
#define FLV_B (64 * AVS * 2)                  //  9216 per buffer
#define FL_SMEM (FLQ_B + 2 * FLK_B + 2 * FLV_B)   // 88064

__global__ void __launch_bounds__(256, 2) flash3_kernel(
    const float* __restrict__ Q, const float* __restrict__ Kg,
    const float* __restrict__ Vg, __nv_bfloat16* __restrict__ O)
{
    extern __shared__ char fsm[];
    float*  Qs = (float*)fsm;
    float*  Kb = (float*)(fsm + FLQ_B);
    __half* Vb = (__half*)(fsm + FLQ_B + 2 * FLK_B);

    const int tid  = threadIdx.x;
    const int lane = tid & 31;
    const int warp = tid >> 5;
    const int bq = blockIdx.x, head = blockIdx.y, b = blockIdx.z;
    const size_t qtok0 = (size_t)b * SEQ + (size_t)bq * 128;
    const size_t ktokb = (size_t)b * SEQ;
    const int col0 = head * HD;
    const int m0 = warp * 16;
    const float QSCALE = 0.125f * 1.4426950408889634f;

    const unsigned qs_u = smem_u32(Qs);
    const unsigned kb_u = smem_u32(Kb);
    const unsigned vb_u = smem_u32(Vb);

    // stage Q (scaled, tf32-rounded), resident for whole kernel
    #pragma unroll
    for (int j = 0; j < 8; j++) {
        int f = tid + j * 256;
        int r = f >> 4, c = (f & 15) * 4;
        float4 v = *(const float4*)(Q + (qtok0 + r) * D_MODEL + col0 + c);
        float4 t;
        t.x = __uint_as_float(f2tf(v.x * QSCALE));
        t.y = __uint_as_float(f2tf(v.y * QSCALE));
        t.z = __uint_as_float(f2tf(v.z * QSCALE));
        t.w = __uint_as_float(f2tf(v.w * QSCALE));
        *(float4*)(Qs + r * AQS + c) = t;
    }

    // K tile 0 via cp.async (raw fp32; HW truncates to tf32 in the MMA)
    #pragma unroll
    for (int j = 0; j < 4; j++) {
        int id = tid + j * 256;
        int r = id >> 4, c = (id & 15) * 4;
        cp16(kb_u + (r * AQS + c) * 4, Kg + (ktokb + r) * D_MODEL + col0 + c);
    }
    CP_COMMIT();
    // V tile 0 via registers (needs f16 conversion)
    #pragma unroll
    for (int j = 0; j < 4; j++) {
        int f = tid + j * 256;
        int r = f >> 4, c = (f & 15) * 4;
        float4 vv = *(const float4*)(Vg + (ktokb + r) * D_MODEL + col0 + c);
        *(__half2*)(Vb + r * AVS + c)     = __floats2half2_rn(vv.x, vv.y);
        *(__half2*)(Vb + r * AVS + c + 2) = __floats2half2_rn(vv.z, vv.w);
    }
    CP_WAIT0();
    __syncthreads();

    float m0s = -INFINITY, m1s = -INFINITY, l0s = 0.f, l1s = 0.f;
    float oacc[8][4];
    #pragma unroll
    for (int i = 0; i < 8; i++)
        #pragma unroll
        for (int j = 0; j < 4; j++) oacc[i][j] = 0.f;

    for (int kvt = 0; kvt < SEQ / 64; kvt++) {
        const int buf = kvt & 1;
        const bool pre = (kvt + 1) < SEQ / 64;
        float4 vr[4];
        if (pre) {
            const size_t kt = ktokb + (size_t)(kvt + 1) * 64;
            const unsigned kbd = kb_u + (buf ^ 1) * FLK_B;
            #pragma unroll
            for (int j = 0; j < 4; j++) {
                int id = tid + j * 256;
                int r = id >> 4, c = (id & 15) * 4;
                cp16(kbd + (r * AQS + c) * 4, Kg + (kt + r) * D_MODEL + col0 + c);
                vr[j] = *(const float4*)(Vg + (kt + r) * D_MODEL + col0 + c);
            }
        }
        CP_COMMIT();

        // ---- S = Q @ K^T (tf32; Q A-frags re-ldsm'd from resident Qs) ----
        float sacc[8][4];
        #pragma unroll
        for (int i = 0; i < 8; i++)
            #pragma unroll
            for (int j = 0; j < 4; j++) sacc[i][j] = 0.f;

        const unsigned kfb = kb_u + buf * FLK_B;
        #pragma unroll
        for (int k0 = 0; k0 < 8; k0++) {
            unsigned qa0, qa1, qa2, qa3;
            ldsm_x4(qa0, qa1, qa2, qa3,
                    qs_u + ((m0 + (lane & 15)) * AQS + k0 * 8 + (lane >> 4) * 4) * 4);
            unsigned qa[4] = {qa0, qa1, qa2, qa3};
            #pragma unroll
            for (int nf2 = 0; nf2 < 4; nf2++) {
                const int midx = lane >> 3;
                unsigned addr = kfb +
                    ((nf2 * 16 + (midx >> 1) * 8 + (lane & 7)) * AQS +
                     k0 * 8 + (midx & 1) * 4) * 4;
                unsigned b0, b1, b2, b3;
                ldsm_x4(b0, b1, b2, b3, addr);
                mma_tf32(sacc[nf2 * 2],     qa, b0, b1);
                mma_tf32(sacc[nf2 * 2 + 1], qa, b2, b3);
            }
        }

        // ---- online softmax ----
        float mx0 = -INFINITY, mx1 = -INFINITY;
        #pragma unroll
        for (int nf = 0; nf < 8; nf++) {
            mx0 = fmaxf(mx0, fmaxf(sacc[nf][0], sacc[nf][1]));
            mx1 = fmaxf(mx1, fmaxf(sacc[nf][2], sacc[nf][3]));
        }
        mx0 = fmaxf(mx0, __shfl_xor_sync(0xffffffffu, mx0, 1));
        mx0 = fmaxf(mx0, __shfl_xor_sync(0xffffffffu, mx0, 2));
        mx1 = fmaxf(mx1, __shfl_xor_sync(0xffffffffu, mx1, 1));
        mx1 = fmaxf(mx1, __shfl_xor_sync(0xffffffffu, mx1, 2));

        const float mn0 = fmaxf(m0s, mx0);
        const float mn1 = fmaxf(m1s, mx1);
        const float al0 = ex2f(m0s - mn0);
        const float al1 = ex2f(m1s - mn1);

        unsigned pa0[8], pa1[8];
        float ls0 = 0.f, ls1 = 0.f;
        #pragma unroll
        for (int nf = 0; nf < 8; nf++) {
            float p0 = ex2f(sacc[nf][0] - mn0);
            float p1 = ex2f(sacc[nf][1] - mn0);
            float p2 = ex2f(sacc[nf][2] - mn1);
            float p3 = ex2f(sacc[nf][3] - mn1);
            ls0 += p0 + p1;
            ls1 += p2 + p3;
            pa0[nf] = packh2(p0, p1);
            pa1[nf] = packh2(p2, p3);
        }
        ls0 += __shfl_xor_sync(0xffffffffu, ls0, 1);
        ls0 += __shfl_xor_sync(0xffffffffu, ls0, 2);
        ls1 += __shfl_xor_sync(0xffffffffu, ls1, 1);
        ls1 += __shfl_xor_sync(0xffffffffu, ls1, 2);
        l0s = l0s * al0 + ls0;
        l1s = l1s * al1 + ls1;
        m0s = mn0; m1s = mn1;

        #pragma unroll
        for (int nf = 0; nf < 8; nf++) {
            oacc[nf][0] *= al0; oacc[nf][1] *= al0;
            oacc[nf][2] *= al1; oacc[nf][3] *= al1;
        }

        // ---- O += P @ V (f16) ----
        const unsigned vhb = vb_u + buf * FLV_B;
        #pragma unroll
        for (int ks = 0; ks < 4; ks++) {
            unsigned a0 = pa0[2 * ks],     a1 = pa1[2 * ks];
            unsigned a2 = pa0[2 * ks + 1], a3 = pa1[2 * ks + 1];
            #pragma unroll
            for (int no = 0; no < 4; no++) {
                unsigned addr = vhb +
                    ((ks * 16 + (lane & 15)) * AVS + no * 16 + (lane >> 4) * 8) * 2;
                unsigned b0, b1, b2, b3;
                ldsm_x4_t(b0, b1, b2, b3, addr);
                mma_f16(oacc[no * 2],     a0, a1, a2, a3, b0, b1);
                mma_f16(oacc[no * 2 + 1], a0, a1, a2, a3, b2, b3);
            }
        }

        if (pre) {
            __half* Vhd = Vb + (buf ^ 1) * 64 * AVS;
            #pragma unroll
            for (int j = 0; j < 4; j++) {
                int id = tid + j * 256;
                int r = id >> 4, c = (id & 15) * 4;
                *(__half2*)(Vhd + r * AVS + c)     = __floats2half2_rn(vr[j].x, vr[j].y);
                *(__half2*)(Vhd + r * AVS + c + 2) = __floats2half2_rn(vr[j].z, vr[j].w);
            }
        }
        CP_WAIT0();
        __syncthreads();
    }

    const float i0 = 1.f / l0s;
    const float i1 = 1.f / l1s;
    const size_t row0 = qtok0 + m0 + (lane >> 2);
    #pragma unroll
    for (int no = 0; no < 8; no++) {
        const int cw = col0 + no * 8 + (lane & 3) * 2;
        *(__nv_bfloat162*)(O + row0 * D_MODEL + cw) =
            __floats2bfloat162_rn(oacc[no][0] * i0, oacc[no][1] * i0);
        *(__nv_bfloat162*)(O + (row0 + 8) * D_MODEL + cw) =
            __floats2bfloat162_rn(oacc[no][2] * i1, oacc[no][3] * i1);
    }
}

// ---------------- driver ----------------------------------------------------
extern "C" void kernel_launch(void* const* d_in, const int* in_sizes, int n_in,
                              void* d_out, int out_size)
{
    const float* x       = (const float*)d_in[0];
    const float* W_q     = (const float*)d_in[1];
    const float* W_k     = (const float*)d_in[2];
    const float* W_v     = (const float*)d_in[3];
    const float* W_o     = (const float*)d_in[4];
    const float* b_o     = (const float*)d_in[5];
    const float* a_nw    = (const float*)d_in[6];
    const float* f_nw    = (const float*)d_in[7];
    const float* W_gate  = (const float*)d_in[8];
    const float* W_hid   = (const float*)d_in[9];
    const float* W_out   = (const float*)d_in[10];
    const float* b_out   = (const float*)d_in[11];
    float* out = (float*)d_out;

    float *q, *k, *v, *x1;
    __nv_bfloat16 *xnb, *atb, *hb, *wq, *wk, *wv, *wo, *wg, *wh, *wd;
    cudaGetSymbolAddress((void**)&q,   g_q);
    cudaGetSymbolAddress((void**)&k,   g_k);
    cudaGetSymbolAddress((void**)&v,   g_v);
    cudaGetSymbolAddress((void**)&x1,  g_x1);
    cudaGetSymbolAddress((void**)&xnb, g_xnb);
    cudaGetSymbolAddress((void**)&atb, g_atb);
    cudaGetSymbolAddress((void**)&hb,  g_hb);
    cudaGetSymbolAddress((void**)&wq,  g_wq);
    cudaGetSymbolAddress((void**)&wk,  g_wk);
    cudaGetSymbolAddress((void**)&wv,  g_wv);
    cudaGetSymbolAddress((void**)&wo,  g_wo);
    cudaGetSymbolAddress((void**)&wg,  g_wg);
    cudaGetSymbolAddress((void**)&wh,  g_wh);
    cudaGetSymbolAddress((void**)&wd,  g_wd);

    cudaFuncSetAttribute(flash3_kernel,
                         cudaFuncAttributeMaxDynamicSharedMemorySize, FL_SMEM);
    cudaFuncSetAttribute(mma_gemm_kernel,
                         cudaFuncAttributeMaxDynamicSharedMemorySize, G5_SMEM);
    cudaFuncSetAttribute(mma_gemm_multi,
                         cudaFuncAttributeMaxDynamicSharedMemorySize, G5_SMEM);
    cudaFuncSetAttribute(swiglu_gemm_kernel,
                         cudaFuncAttributeMaxDynamicSharedMemorySize, SWI_SMEM);

    // 0) convert weights to bf16 [K,N]
    dim3 gc(1024, 16);
    cvt_w_kernel<<<gc, 256>>>(W_q, W_k, W_v, W_o, W_gate, W_hid, W_out,
                              wq, wk, wv, wo, wg, wh, wd);

    // 1) attn rmsnorm -> bf16
    rmsnorm_kernel<<<N_TOK, 256>>>(x, a_nw, xnb);

    // 2) q, k, v projections (batched)
    dim3 gqkv(D_MODEL / 128, N_TOK / 128, 3);
    mma_gemm_multi<<<gqkv, 256, G5_SMEM>>>(xnb, wq, wk, wv, q, k, v,
                                           N_TOK, D_MODEL, D_MODEL);

    // 3) attention -> bf16
    dim3 ga(SEQ / 128, N_HEADS, 2);
    flash3_kernel<<<ga, 256, FL_SMEM>>>(q, k, v, atb);

    // 4) output projection + bias + residual
    dim3 gd(D_MODEL / 128, N_TOK / 128);
    mma_gemm_kernel<<<gd, 256, G5_SMEM>>>(atb, wo, b_o, x, x1,
                                          N_TOK, D_MODEL, D_MODEL);

    // 5) ffn rmsnorm -> bf16
    rmsnorm_kernel<<<N_TOK, 256>>>(x1, f_nw, xnb);

    // 6+7) fused gate/hidden GEMMs + SwiGLU -> hb bf16
    dim3 gf(D_FF / 128, N_TOK / 128);
    swiglu_gemm_kernel<<<gf, 256, SWI_SMEM>>>(xnb, wg, wh, hb,
                                              N_TOK, D_FF, D_MODEL);

    // 8) down projection + bias + residual -> out
    mma_gemm_kernel<<<gd, 256, G5_SMEM>>>(hb, wd, b_out, x1, out,
                                          N_TOK, D_MODEL, D_FF);
}

// round 7
// speedup vs baseline: 6.9096x; 1.0857x over previous
#include <cuda_runtime.h>
#include <cuda_fp16.h>
#include <cuda_bf16.h>
#include <math.h>

#define D_MODEL 1024
#define N_TOK   4096
#define N_HEADS 16
#define HD      64
#define D_FF    4096
#define SEQ     2048

// ---------------- scratch (device globals; no allocation allowed) ----------
__device__ __half g_qh[N_TOK * D_MODEL];
__device__ __half g_kh[N_TOK * D_MODEL];
__device__ __half g_vh[N_TOK * D_MODEL];
__device__ float  g_x1[N_TOK * D_MODEL];
__device__ __nv_bfloat16 g_xnb[N_TOK * D_MODEL];
__device__ __nv_bfloat16 g_atb[N_TOK * D_MODEL];
__device__ __nv_bfloat16 g_hb [N_TOK * D_FF];
// bf16 weights, [K, N] layout (as given)
__device__ __nv_bfloat16 g_wq[D_MODEL * D_MODEL];
__device__ __nv_bfloat16 g_wk[D_MODEL * D_MODEL];
__device__ __nv_bfloat16 g_wv[D_MODEL * D_MODEL];
__device__ __nv_bfloat16 g_wo[D_MODEL * D_MODEL];
__device__ __nv_bfloat16 g_wg[D_MODEL * D_FF];
__device__ __nv_bfloat16 g_wh[D_MODEL * D_FF];
__device__ __nv_bfloat16 g_wd[D_FF * D_MODEL];

// ---------------- helpers ---------------------------------------------------
__device__ __forceinline__ unsigned smem_u32(const void* p) {
    unsigned a;
    asm("{ .reg .u64 t; cvta.to.shared.u64 t, %1; cvt.u32.u64 %0, t; }"
        : "=r"(a) : "l"(p));
    return a;
}
__device__ __forceinline__ float ex2f(float x) {
    float y;
    asm("ex2.approx.ftz.f32 %0, %1;" : "=f"(y) : "f"(x));
    return y;
}
__device__ __forceinline__ unsigned packh2(float lo, float hi) {
    unsigned d;
    asm("cvt.rn.f16x2.f32 %0, %1, %2;" : "=r"(d) : "f"(hi), "f"(lo));
    return d;
}
__device__ __forceinline__ void ldsm_x4(unsigned& r0, unsigned& r1,
                                        unsigned& r2, unsigned& r3, unsigned addr) {
    asm volatile("ldmatrix.sync.aligned.m8n8.x4.shared.b16 {%0,%1,%2,%3}, [%4];"
                 : "=r"(r0), "=r"(r1), "=r"(r2), "=r"(r3) : "r"(addr));
}
__device__ __forceinline__ void ldsm_x4_t(unsigned& r0, unsigned& r1,
                                          unsigned& r2, unsigned& r3, unsigned addr) {
    asm volatile("ldmatrix.sync.aligned.m8n8.x4.trans.shared.b16 {%0,%1,%2,%3}, [%4];"
                 : "=r"(r0), "=r"(r1), "=r"(r2), "=r"(r3) : "r"(addr));
}
__device__ __forceinline__ void mma_f16(float* d, unsigned a0, unsigned a1,
                                        unsigned a2, unsigned a3,
                                        unsigned b0, unsigned b1) {
    asm volatile(
        "mma.sync.aligned.m16n8k16.row.col.f32.f16.f16.f32 "
        "{%0,%1,%2,%3}, {%4,%5,%6,%7}, {%8,%9}, {%0,%1,%2,%3};"
        : "+f"(d[0]), "+f"(d[1]), "+f"(d[2]), "+f"(d[3])
        : "r"(a0), "r"(a1), "r"(a2), "r"(a3), "r"(b0), "r"(b1));
}
__device__ __forceinline__ void mma_bf16(float* d, unsigned a0, unsigned a1,
                                         unsigned a2, unsigned a3,
                                         unsigned b0, unsigned b1) {
    asm volatile(
        "mma.sync.aligned.m16n8k16.row.col.f32.bf16.bf16.f32 "
        "{%0,%1,%2,%3}, {%4,%5,%6,%7}, {%8,%9}, {%0,%1,%2,%3};"
        : "+f"(d[0]), "+f"(d[1]), "+f"(d[2]), "+f"(d[3])
        : "r"(a0), "r"(a1), "r"(a2), "r"(a3), "r"(b0), "r"(b1));
}
__device__ __forceinline__ void cp16(unsigned dst, const void* src) {
    asm volatile("cp.async.cg.shared.global [%0], [%1], 16;"
                 :: "r"(dst), "l"(src));
}
#define CP_COMMIT() asm volatile("cp.async.commit_group;")
#define CP_WAIT0()  asm volatile("cp.async.wait_group 0;")

// ---------------- weight fp32 -> bf16 conversion (keeps [K,N]) -------------
__global__ void __launch_bounds__(256) cvt_w_kernel(
    const float* __restrict__ wq, const float* __restrict__ wk,
    const float* __restrict__ wv, const float* __restrict__ wo,
    const float* __restrict__ wg, const float* __restrict__ wh,
    const float* __restrict__ wd,
    __nv_bfloat16* oq, __nv_bfloat16* ok, __nv_bfloat16* ov, __nv_bfloat16* oo,
    __nv_bfloat16* og, __nv_bfloat16* oh, __nv_bfloat16* od)
{
    int z = blockIdx.y;
    const float* s;
    __nv_bfloat16* d;
    size_t off;
    if (z < 4)       { s = (z==0)?wq:(z==1)?wk:(z==2)?wv:wo;
                       d = (z==0)?oq:(z==1)?ok:(z==2)?ov:oo; off = 0; }
    else if (z < 8)  { s = wg; d = og; off = (size_t)(z - 4)  << 20; }
    else if (z < 12) { s = wh; d = oh; off = (size_t)(z - 8)  << 20; }
    else             { s = wd; d = od; off = (size_t)(z - 12) << 20; }
    size_t i = blockIdx.x * 256 + threadIdx.x;
    float4 v = ((const float4*)(s + off))[i];
    __nv_bfloat162* dp = (__nv_bfloat162*)(d + off);
    dp[i * 2]     = __floats2bfloat162_rn(v.x, v.y);
    dp[i * 2 + 1] = __floats2bfloat162_rn(v.z, v.w);
}

// ---------------- rmsnorm: fp32 in, bf16 out -------------------------------
__global__ void __launch_bounds__(256) rmsnorm_kernel(
    const float* __restrict__ x, const float* __restrict__ w,
    __nv_bfloat16* __restrict__ y)
{
    int row = blockIdx.x;
    int t   = threadIdx.x;
    const float4* xr = (const float4*)(x + (size_t)row * D_MODEL);
    float4 v = xr[t];
    float ss = v.x * v.x + v.y * v.y + v.z * v.z + v.w * v.w;
    #pragma unroll
    for (int m = 16; m; m >>= 1) ss += __shfl_xor_sync(0xffffffffu, ss, m);
    __shared__ float red[8];
    if ((t & 31) == 0) red[t >> 5] = ss;
    __syncthreads();
    float tot = 0.f;
    #pragma unroll
    for (int i = 0; i < 8; i++) tot += red[i];
    float r = rsqrtf(tot * (1.0f / D_MODEL) + 1e-6f);
    float4 wv = ((const float4*)w)[t];
    __nv_bfloat162* yr = (__nv_bfloat162*)(y + (size_t)row * D_MODEL) + t * 2;
    yr[0] = __floats2bfloat162_rn(v.x * wv.x * r, v.y * wv.y * r);
    yr[1] = __floats2bfloat162_rn(v.z * wv.z * r, v.w * wv.w * r);
}

// ---------------- bf16 HMMA GEMM core: multi-stage cp.async ----------------
#define BKh 32
#define SAh 40
#define SBh 136
#define ASTG (128 * SAh)
#define BSTG (BKh * SBh)
#define STG_B ((ASTG + BSTG) * 2)
#define G5_SMEM (5 * STG_B)
#define SWI_STASH (256 * 33 * 4)
#define SWI_SMEM (4 * STG_B + SWI_STASH)

template<int NSTG>
__device__ __forceinline__ void gemm_kloop(
    const __nv_bfloat16* __restrict__ Ab,
    const __nv_bfloat16* __restrict__ Bb,
    int N, int K, unsigned as_u, unsigned bs_u,
    float (&acc)[4][4][4], int tid, int lane, int wm, int wn)
{
    const int arow = tid >> 1, acolh = (tid & 1) * 16;
    const int brow = tid >> 3, bcolh = (tid & 7) * 16;
    const __nv_bfloat16* Ag = Ab + (size_t)arow * K + acolh;
    const __nv_bfloat16* Bg = Bb + (size_t)brow * N + bcolh;
    const unsigned adst = as_u + (arow * SAh + acolh) * 2;
    const unsigned bdst = bs_u + (brow * SBh + bcolh) * 2;
    const int KC = K / BKh;

    #pragma unroll
    for (int s = 0; s < NSTG - 1; s++) {
        const __nv_bfloat16* ag = Ag + s * BKh;
        const __nv_bfloat16* bg = Bg + (size_t)s * BKh * N;
        cp16(adst + s * ASTG * 2, ag);
        cp16(adst + s * ASTG * 2 + 16, ag + 8);
        cp16(bdst + s * BSTG * 2, bg);
        cp16(bdst + s * BSTG * 2 + 16, bg + 8);
        CP_COMMIT();
    }

    for (int c = 0; c < KC; c++) {
        asm volatile("cp.async.wait_group %0;" :: "n"(NSTG - 2));
        __syncthreads();

        if (c + NSTG - 1 < KC) {
            const int s = (c + NSTG - 1) % NSTG;
            const __nv_bfloat16* ag = Ag + (c + NSTG - 1) * BKh;
            const __nv_bfloat16* bg = Bg + (size_t)(c + NSTG - 1) * BKh * N;
            cp16(adst + s * ASTG * 2, ag);
            cp16(adst + s * ASTG * 2 + 16, ag + 8);
            cp16(bdst + s * BSTG * 2, bg);
            cp16(bdst + s * BSTG * 2 + 16, bg + 8);
        }
        CP_COMMIT();

        const int s = c % NSTG;
        const unsigned asb = as_u + s * ASTG * 2;
        const unsigned bsb = bs_u + s * BSTG * 2;
        #pragma unroll
        for (int ks = 0; ks < 2; ks++) {
            const int k0 = ks * 16;
            unsigned a[4][4];
            #pragma unroll
            for (int mf = 0; mf < 4; mf++) {
                unsigned addr = asb +
                    ((wm + mf * 16 + (lane & 15)) * SAh + k0 + (lane >> 4) * 8) * 2;
                ldsm_x4(a[mf][0], a[mf][1], a[mf][2], a[mf][3], addr);
            }
            unsigned b[2][4];
            #pragma unroll
            for (int nb = 0; nb < 2; nb++) {
                unsigned addr = bsb +
                    ((k0 + (lane & 15)) * SBh + wn + nb * 16 + (lane >> 4) * 8) * 2;
                ldsm_x4_t(b[nb][0], b[nb][1], b[nb][2], b[nb][3], addr);
            }
            #pragma unroll
            for (int mf = 0; mf < 4; mf++)
                #pragma unroll
                for (int nf = 0; nf < 4; nf++)
                    mma_bf16(acc[mf][nf], a[mf][0], a[mf][1], a[mf][2], a[mf][3],
                             b[nf >> 1][(nf & 1) * 2], b[nf >> 1][(nf & 1) * 2 + 1]);
        }
    }
}

__device__ __forceinline__ void gemm_epilogue(
    float (&acc)[4][4][4], const float* bias, const float* res,
    float* C, int N, int row0, int col0, int lane, int wm, int wn)
{
    #pragma unroll
    for (int mf = 0; mf < 4; mf++) {
        const int r = row0 + wm + mf * 16 + (lane >> 2);
        #pragma unroll
        for (int nf = 0; nf < 4; nf++) {
            const int cc = col0 + wn + nf * 8 + (lane & 3) * 2;
            float2 v0 = make_float2(acc[mf][nf][0], acc[mf][nf][1]);
            float2 v1 = make_float2(acc[mf][nf][2], acc[mf][nf][3]);
            if (bias) {
                float2 bv = *(const float2*)(bias + cc);
                v0.x += bv.x; v0.y += bv.y;
                v1.x += bv.x; v1.y += bv.y;
            }
            if (res) {
                float2 r0 = *(const float2*)(res + (size_t)r * N + cc);
                float2 r1 = *(const float2*)(res + (size_t)(r + 8) * N + cc);
                v0.x += r0.x; v0.y += r0.y;
                v1.x += r1.x; v1.y += r1.y;
            }
            *(float2*)(C + (size_t)r * N + cc) = v0;
            *(float2*)(C + (size_t)(r + 8) * N + cc) = v1;
        }
    }
}

__global__ void __launch_bounds__(256, 2) mma_gemm_kernel(
    const __nv_bfloat16* __restrict__ A, const __nv_bfloat16* __restrict__ B,
    const float* __restrict__ bias, const float* __restrict__ res,
    float* __restrict__ C, int M, int N, int K)
{
    extern __shared__ __nv_bfloat16 smh[];
    const unsigned as_u = smem_u32(smh);
    const int tid = threadIdx.x, lane = tid & 31, warp = tid >> 5;
    const int wm = (warp >> 2) * 64, wn = (warp & 3) * 32;
    const int row0 = blockIdx.y * 128, col0 = blockIdx.x * 128;
    float acc[4][4][4];
    #pragma unroll
    for (int i = 0; i < 4; i++)
        #pragma unroll
        for (int j = 0; j < 4; j++)
            #pragma unroll
            for (int r = 0; r < 4; r++) acc[i][j][r] = 0.f;
    gemm_kloop<5>(A + (size_t)row0 * K, B + col0, N, K,
                  as_u, as_u + 5 * ASTG * 2, acc, tid, lane, wm, wn);
    gemm_epilogue(acc, bias, res, C, N, row0, col0, lane, wm, wn);
}

// QKV projections: writes f16 outputs for the attention kernel
__global__ void __launch_bounds__(256, 2) mma_gemm_multi_h(
    const __nv_bfloat16* __restrict__ A,
    const __nv_bfloat16* __restrict__ B0, const __nv_bfloat16* __restrict__ B1,
    const __nv_bfloat16* __restrict__ B2,
    __half* __restrict__ C0, __half* __restrict__ C1, __half* __restrict__ C2,
    int M, int N, int K)
{
    extern __shared__ __nv_bfloat16 smh[];
    const unsigned as_u = smem_u32(smh);
    const __nv_bfloat16* B = (blockIdx.z == 0) ? B0 : (blockIdx.z == 1) ? B1 : B2;
    __half*              C = (blockIdx.z == 0) ? C0 : (blockIdx.z == 1) ? C1 : C2;
    const int tid = threadIdx.x, lane = tid & 31, warp = tid >> 5;
    const int wm = (warp >> 2) * 64, wn = (warp & 3) * 32;
    const int row0 = blockIdx.y * 128, col0 = blockIdx.x * 128;
    float acc[4][4][4];
    #pragma unroll
    for (int i = 0; i < 4; i++)
        #pragma unroll
        for (int j = 0; j < 4; j++)
            #pragma unroll
            for (int r = 0; r < 4; r++) acc[i][j][r] = 0.f;
    gemm_kloop<5>(A + (size_t)row0 * K, B + col0, N, K,
                  as_u, as_u + 5 * ASTG * 2, acc, tid, lane, wm, wn);
    #pragma unroll
    for (int mf = 0; mf < 4; mf++) {
        const int r = row0 + wm + mf * 16 + (lane >> 2);
        #pragma unroll
        for (int nf = 0; nf < 4; nf++) {
            const int cc = col0 + wn + nf * 8 + (lane & 3) * 2;
            *(__half2*)(C + (size_t)r * N + cc) =
                __floats2half2_rn(acc[mf][nf][0], acc[mf][nf][1]);
            *(__half2*)(C + (size_t)(r + 8) * N + cc) =
                __floats2half2_rn(acc[mf][nf][2], acc[mf][nf][3]);
        }
    }
}

// ---------------- fused SwiGLU GEMM: hb = bf16(silu(A@Wg) * (A@Wh)) --------
__global__ void __launch_bounds__(256, 2) swiglu_gemm_kernel(
    const __nv_bfloat16* __restrict__ A,
    const __nv_bfloat16* __restrict__ Wg, const __nv_bfloat16* __restrict__ Wh,
    __nv_bfloat16* __restrict__ hb, int M, int N, int K)
{
    extern __shared__ __nv_bfloat16 smh[];
    const unsigned as_u = smem_u32(smh);
    const unsigned bs_u = as_u + 4 * ASTG * 2;
    unsigned* stash = (unsigned*)((char*)smh + 4 * STG_B);

    const int tid = threadIdx.x, lane = tid & 31, warp = tid >> 5;
    const int wm = (warp >> 2) * 64, wn = (warp & 3) * 32;
    const int row0 = blockIdx.y * 128, col0 = blockIdx.x * 128;

    float acc[4][4][4];
    #pragma unroll
    for (int i = 0; i < 4; i++)
        #pragma unroll
        for (int j = 0; j < 4; j++)
            #pragma unroll
            for (int r = 0; r < 4; r++) acc[i][j][r] = 0.f;

    gemm_kloop<4>(A + (size_t)row0 * K, Wg + col0, N, K,
                  as_u, bs_u, acc, tid, lane, wm, wn);

    unsigned* st = stash + tid * 33;
    #pragma unroll
    for (int mf = 0; mf < 4; mf++)
        #pragma unroll
        for (int nf = 0; nf < 4; nf++) {
            float s0 = acc[mf][nf][0]; s0 = s0 / (1.f + __expf(-s0));
            float s1 = acc[mf][nf][1]; s1 = s1 / (1.f + __expf(-s1));
            float s2 = acc[mf][nf][2]; s2 = s2 / (1.f + __expf(-s2));
            float s3 = acc[mf][nf][3]; s3 = s3 / (1.f + __expf(-s3));
            __nv_bfloat162 p0 = __floats2bfloat162_rn(s0, s1);
            __nv_bfloat162 p1 = __floats2bfloat162_rn(s2, s3);
            st[mf * 8 + nf * 2]     = *(unsigned*)&p0;
            st[mf * 8 + nf * 2 + 1] = *(unsigned*)&p1;
        }

    __syncthreads();

    #pragma unroll
    for (int i = 0; i < 4; i++)
        #pragma unroll
        for (int j = 0; j < 4; j++)
            #pragma unroll
            for (int r = 0; r < 4; r++) acc[i][j][r] = 0.f;

    gemm_kloop<4>(A + (size_t)row0 * K, Wh + col0, N, K,
                  as_u, bs_u, acc, tid, lane, wm, wn);

    #pragma unroll
    for (int mf = 0; mf < 4; mf++) {
        const int r = row0 + wm + mf * 16 + (lane >> 2);
        #pragma unroll
        for (int nf = 0; nf < 4; nf++) {
            const int cc = col0 + wn + nf * 8 + (lane & 3) * 2;
            unsigned p0 = st[mf * 8 + nf * 2];
            unsigned p1 = st[mf * 8 + nf * 2 + 1];
            float g0 = __uint_as_float(p0 << 16);
            float g1 = __uint_as_float(p0 & 0xffff0000u);
            float g2 = __uint_as_float(p1 << 16);
            float g3 = __uint_as_float(p1 & 0xffff0000u);
            *(__nv_bfloat162*)(hb + (size_t)r * N + cc) =
                __floats2bfloat162_rn(g0 * acc[mf][nf][0], g1 * acc[mf][nf][1]);
            *(__nv_bfloat162*)(hb + (size_t)(r + 8) * N + cc) =
                __floats2bfloat162_rn(g2 * acc[mf][nf][2], g3 * acc[mf][nf][3]);
        }
    }
}

// ---------------- flash attention v4: all-f16 tensor path ------------------
// Q/K/V f16 in gmem. Q resident smem; K,V double-buffered via cp.async.
// S = Q@K^T with mma.m16n8k16.f16 (full rate); scale applied post-MMA.
#define QH 72                             // smem row stride (halves)
#define FQ_B (128 * QH * 2)               // 18432
#define FK_B (64 * QH * 2)                //  9216 per buffer
#define FL_SMEM (FQ_B + 4 * FK_B)         // 55296

__global__ void __launch_bounds__(256, 2) flash4_kernel(
    const __half* __restrict__ Qh, const __half* __restrict__ Kh,
    const __half* __restrict__ Vh, __nv_bfloat16* __restrict__ O)
{
    extern __shared__ char fsm[];
    const unsigned qs_u = smem_u32(fsm);
    const unsigned kb_u = qs_u + FQ_B;
    const unsigned vb_u = qs_u + FQ_B + 2 * FK_B;

    const int tid  = threadIdx.x;
    const int lane = tid & 31;
    const int warp = tid >> 5;
    const int bq = blockIdx.x, head = blockIdx.y, b = blockIdx.z;
    const size_t qtok0 = (size_t)b * SEQ + (size_t)bq * 128;
    const size_t ktokb = (size_t)b * SEQ;
    const int col0 = head * HD;
    const int m0 = warp * 16;
    const float SC = 0.125f * 1.4426950408889634f;   // 1/sqrt(64) * log2(e)

    // prologue: Q resident + K/V tile 0, all via cp.async
    #pragma unroll
    for (int j = 0; j < 4; j++) {
        int id = tid + j * 256;
        int r = id >> 3, c = (id & 7) * 8;
        cp16(qs_u + (r * QH + c) * 2, Qh + (qtok0 + r) * D_MODEL + col0 + c);
    }
    #pragma unroll
    for (int j = 0; j < 2; j++) {
        int id = tid + j * 256;
        int r = id >> 3, c = (id & 7) * 8;
        cp16(kb_u + (r * QH + c) * 2, Kh + (ktokb + r) * D_MODEL + col0 + c);
        cp16(vb_u + (r * QH + c) * 2, Vh + (ktokb + r) * D_MODEL + col0 + c);
    }
    CP_COMMIT();
    CP_WAIT0();
    __syncthreads();

    float m0s = -INFINITY, m1s = -INFINITY, l0s = 0.f, l1s = 0.f;
    float oacc[8][4];
    #pragma unroll
    for (int i = 0; i < 8; i++)
        #pragma unroll
        for (int j = 0; j < 4; j++) oacc[i][j] = 0.f;

    for (int kvt = 0; kvt < SEQ / 64; kvt++) {
        const int buf = kvt & 1;
        const bool pre = (kvt + 1) < SEQ / 64;
        if (pre) {
            const size_t kt = ktokb + (size_t)(kvt + 1) * 64;
            const unsigned kbd = kb_u + (buf ^ 1) * FK_B;
            const unsigned vbd = vb_u + (buf ^ 1) * FK_B;
            #pragma unroll
            for (int j = 0; j < 2; j++) {
                int id = tid + j * 256;
                int r = id >> 3, c = (id & 7) * 8;
                cp16(kbd + (r * QH + c) * 2, Kh + (kt + r) * D_MODEL + col0 + c);
                cp16(vbd + (r * QH + c) * 2, Vh + (kt + r) * D_MODEL + col0 + c);
            }
        }
        CP_COMMIT();

        // ---- S = Q @ K^T (f16 m16n8k16) ----
        float sacc[8][4];
        #pragma unroll
        for (int i = 0; i < 8; i++)
            #pragma unroll
            for (int j = 0; j < 4; j++) sacc[i][j] = 0.f;

        const unsigned kfb = kb_u + buf * FK_B;
        #pragma unroll
        for (int ks = 0; ks < 4; ks++) {
            const int k0 = ks * 16;
            unsigned a0, a1, a2, a3;
            ldsm_x4(a0, a1, a2, a3,
                    qs_u + ((m0 + (lane & 15)) * QH + k0 + (lane >> 4) * 8) * 2);
            #pragma unroll
            for (int ng = 0; ng < 4; ng++) {
                unsigned b0, b1, b2, b3;
                ldsm_x4(b0, b1, b2, b3,
                        kfb + ((ng * 16 + (lane & 15)) * QH + k0 + (lane >> 4) * 8) * 2);
                mma_f16(sacc[ng * 2],     a0, a1, a2, a3, b0, b2);
                mma_f16(sacc[ng * 2 + 1], a0, a1, a2, a3, b1, b3);
            }
        }
        // apply softmax scale (folded with log2 e)
        #pragma unroll
        for (int nf = 0; nf < 8; nf++) {
            sacc[nf][0] *= SC; sacc[nf][1] *= SC;
            sacc[nf][2] *= SC; sacc[nf][3] *= SC;
        }

        // ---- online softmax ----
        float mx0 = -INFINITY, mx1 = -INFINITY;
        #pragma unroll
        for (int nf = 0; nf < 8; nf++) {
            mx0 = fmaxf(mx0, fmaxf(sacc[nf][0], sacc[nf][1]));
            mx1 = fmaxf(mx1, fmaxf(sacc[nf][2], sacc[nf][3]));
        }
        mx0 = fmaxf(mx0, __shfl_xor_sync(0xffffffffu, mx0, 1));
        mx0 = fmaxf(mx0, __shfl_xor_sync(0xffffffffu, mx0, 2));
        mx1 = fmaxf(mx1, __shfl_xor_sync(0xffffffffu, mx1, 1));
        mx1 = fmaxf(mx1, __shfl_xor_sync(0xffffffffu, mx1, 2));

        const float mn0 = fmaxf(m0s, mx0);
        const float mn1 = fmaxf(m1s, mx1);
        const float al0 = ex2f(m0s - mn0);
        const float al1 = ex2f(m1s - mn1);

        unsigned pa0[8], pa1[8];
        float ls0 = 0.f, ls1 = 0.f;
        #pragma unroll
        for (int nf = 0; nf < 8; nf++) {
            float p0 = ex2f(sacc[nf][0] - mn0);
            float p1 = ex2f(sacc[nf][1] - mn0);
            float p2 = ex2f(sacc[nf][2] - mn1);
            float p3 = ex2f(sacc[nf][3] - mn1);
            ls0 += p0 + p1;
            ls1 += p2 + p3;
            pa0[nf] = packh2(p0, p1);
            pa1[nf] = packh2(p2, p3);
        }
        ls0 += __shfl_xor_sync(0xffffffffu, ls0, 1);
        ls0 += __shfl_xor_sync(0xffffffffu, ls0, 2);
        ls1 += __shfl_xor_sync(0xffffffffu, ls1, 1);
        ls1 += __shfl_xor_sync(0xffffffffu, ls1, 2);
        l0s = l0s * al0 + ls0;
        l1s = l1s * al1 + ls1;
        m0s = mn0; m1s = mn1;

        #pragma unroll
        for (int nf = 0; nf < 8; nf++) {
            oacc[nf][0] *= al0; oacc[nf][1] *= al0;
            oacc[nf][2] *= al1; oacc[nf][3] *= al1;
        }

        // ---- O += P @ V (f16; V B-frags via ldmatrix.trans) ----
        const unsigned vhb = vb_u + buf * FK_B;
        #pragma unroll
        for (int ks = 0; ks < 4; ks++) {
            unsigned a0 = pa0[2 * ks],     a1 = pa1[2 * ks];
            unsigned a2 = pa0[2 * ks + 1], a3 = pa1[2 * ks + 1];
            #pragma unroll
            for (int no = 0; no < 4; no++) {
                unsigned addr = vhb +
                    ((ks * 16 + (lane & 15)) * QH + no * 16 + (lane >> 4) * 8) * 2;
                unsigned b0, b1, b2, b3;
                ldsm_x4_t(b0, b1, b2, b3, addr);
                mma_f16(oacc[no * 2],     a0, a1, a2, a3, b0, b1);
                mma_f16(oacc[no * 2 + 1], a0, a1, a2, a3, b2, b3);
            }
        }

        CP_WAIT0();
        __syncthreads();
    }

    const float i0 = 1.f / l0s;
    const float i1 = 1.f / l1s;
    const size_t row0 = qtok0 + m0 + (lane >> 2);
    #pragma unroll
    for (int no = 0; no < 8; no++) {
        const int cw = col0 + no * 8 + (lane & 3) * 2;
        *(__nv_bfloat162*)(O + row0 * D_MODEL + cw) =
            __floats2bfloat162_rn(oacc[no][0] * i0, oacc[no][1] * i0);
        *(__nv_bfloat162*)(O + (row0 + 8) * D_MODEL + cw) =
            __floats2bfloat162_rn(oacc[no][2] * i1, oacc[no][3] * i1);
    }
}

// ---------------- driver ----------------------------------------------------
extern "C" void kernel_launch(void* const* d_in, const int* in_sizes, int n_in,
                              void* d_out, int out_size)
{
    const float* x       = (const float*)d_in[0];
    const float* W_q     = (const float*)d_in[1];
    const float* W_k     = (const float*)d_in[2];
    const float* W_v     = (const float*)d_in[3];
    const float* W_o     = (const float*)d_in[4];
    const float* b_o     = (const float*)d_in[5];
    const float* a_nw    = (const float*)d_in[6];
    const float* f_nw    = (const float*)d_in[7];
    const float* W_gate  = (const float*)d_in[8];
    const float* W_hid   = (const float*)d_in[9];
    const float* W_out   = (const float*)d_in[10];
    const float* b_out   = (const float*)d_in[11];
    float* out = (float*)d_out;

    float *x1;
    __half *qh, *kh, *vh;
    __nv_bfloat16 *xnb, *atb, *hb, *wq, *wk, *wv, *wo, *wg, *wh, *wd;
    cudaGetSymbolAddress((void**)&qh,  g_qh);
    cudaGetSymbolAddress((void**)&kh,  g_kh);
    cudaGetSymbolAddress((void**)&vh,  g_vh);
    cudaGetSymbolAddress((void**)&x1,  g_x1);
    cudaGetSymbolAddress((void**)&xnb, g_xnb);
    cudaGetSymbolAddress((void**)&atb, g_atb);
    cudaGetSymbolAddress((void**)&hb,  g_hb);
    cudaGetSymbolAddress((void**)&wq,  g_wq);
    cudaGetSymbolAddress((void**)&wk,  g_wk);
    cudaGetSymbolAddress((void**)&wv,  g_wv);
    cudaGetSymbolAddress((void**)&wo,  g_wo);
    cudaGetSymbolAddress((void**)&wg,  g_wg);
    cudaGetSymbolAddress((void**)&wh,  g_wh);
    cudaGetSymbolAddress((void**)&wd,  g_wd);

    cudaFuncSetAttribute(flash4_kernel,
                         cudaFuncAttributeMaxDynamicSharedMemorySize, FL_SMEM);
    cudaFuncSetAttribute(mma_gemm_kernel,
                         cudaFuncAttributeMaxDynamicSharedMemorySize, G5_SMEM);
    cudaFuncSetAttribute(mma_gemm_multi_h,
                         cudaFuncAttributeMaxDynamicSharedMemorySize, G5_SMEM);
    cudaFuncSetAttribute(swiglu_gemm_kernel,
                         cudaFuncAttributeMaxDynamicSharedMemorySize, SWI_SMEM);

    // 0) convert weights to bf16 [K,N]
    dim3 gc(1024, 16);
    cvt_w_kernel<<<gc, 256>>>(W_q, W_k, W_v, W_o, W_gate, W_hid, W_out,
                              wq, wk, wv, wo, wg, wh, wd);

    // 1) attn rmsnorm -> bf16
    rmsnorm_kernel<<<N_TOK, 256>>>(x, a_nw, xnb);

    // 2) q, k, v projections (batched; f16 outputs)
    dim3 gqkv(D_MODEL / 128, N_TOK / 128, 3);
    mma_gemm_multi_h<<<gqkv, 256, G5_SMEM>>>(xnb, wq, wk, wv, qh, kh, vh,
                                             N_TOK, D_MODEL, D_MODEL);

    // 3) attention -> bf16
    dim3 ga(SEQ / 128, N_HEADS, 2);
    flash4_kernel<<<ga, 256, FL_SMEM>>>(qh, kh, vh, atb);

    // 4) output projection + bias + residual
    dim3 gd(D_MODEL / 128, N_TOK / 128);
    mma_gemm_kernel<<<gd, 256, G5_SMEM>>>(atb, wo, b_o, x, x1,
                                          N_TOK, D_MODEL, D_MODEL);

    // 5) ffn rmsnorm -> bf16
    rmsnorm_kernel<<<N_TOK, 256>>>(x1, f_nw, xnb);

    // 6+7) fused gate/hidden GEMMs + SwiGLU -> hb bf16
    dim3 gf(D_FF / 128, N_TOK / 128);
    swiglu_gemm_kernel<<<gf, 256, SWI_SMEM>>>(xnb, wg, wh, hb,
                                              N_TOK, D_FF, D_MODEL);

    // 8) down projection + bias + residual -> out
    mma_gemm_kernel<<<gd, 256, G5_SMEM>>>(hb, wd, b_out, x1, out,
                                          N_TOK, D_MODEL, D_FF);
}